// round 14
// baseline (speedup 1.0000x reference)
#include <cuda_runtime.h>
#include <cuda_fp16.h>
#include <cstdint>
#include <cstddef>

// ---------------------------------------------------------------------------
// GraphSAGE 2-layer (N=100000, E=800000, 128 -> 128 -> 47, fp32 in/out):
//   prep(detect dtype + fp16 weights + zero + x->fp16) -> adjacency build ->
//   gather([agg|self] fp16) -> GEMM1(fp16 mma, 128-node tiles, 2-stage
//   cp.async, +bias+L2norm+BN) -> BN finalize -> gather(+BN+ReLU) ->
//   GEMM2(fp16 mma, 128-node tiles) -> out
// Device-global pointers always selected INSIDE kernels (GB300 ATS silently
// accepts host shadow addresses of __device__ symbols).
// ---------------------------------------------------------------------------

#define NMAX 100000
#define IWSTR 20         // inS row stride in u32 words (40 halves)
#define SLOTS 64

typedef unsigned long long u64;
typedef unsigned int u32;

__device__ __align__(16) u32  g_x16[(size_t)NMAX * 64];    // x as fp16
__device__ __align__(16) u32  g_h16[(size_t)NMAX * 64];    // h as fp16
__device__ __align__(16) u32  g_in16[(size_t)NMAX * 128];  // [agg|self] fp16
__device__ __align__(16) int  g_cnt[NMAX];
__device__ __align__(16) int  g_slot[(size_t)NMAX * SLOTS];
__device__ __align__(16) u32  g_wT1h[16384];  // fp16 frag-ordered
__device__ __align__(16) u32  g_wT2h[6144];
__device__ __align__(16) float g_bnsum[128];
__device__ __align__(16) float g_bnsq[128];
__device__ __align__(16) float g_bnscale[128];
__device__ __align__(16) float g_bnshift[128];
__device__ int g_ei32;

// ---- helpers ---------------------------------------------------------------
__device__ __forceinline__ void mma_f16(float* c, u32 a0, u32 a1, u32 a2, u32 a3,
                                        u32 b0, u32 b1) {
    asm volatile(
        "mma.sync.aligned.m16n8k16.row.col.f32.f16.f16.f32 "
        "{%0,%1,%2,%3}, {%4,%5,%6,%7}, {%8,%9}, {%0,%1,%2,%3};"
        : "+f"(c[0]), "+f"(c[1]), "+f"(c[2]), "+f"(c[3])
        : "r"(a0), "r"(a1), "r"(a2), "r"(a3), "r"(b0), "r"(b1));
}
__device__ __forceinline__ void cpa16(void* smem, const void* g) {
    u32 s = (u32)__cvta_generic_to_shared(smem);
    asm volatile("cp.async.cg.shared.global [%0], [%1], 16;" :: "r"(s), "l"(g));
}
__device__ __forceinline__ void cpa16_zero(void* smem, const void* g) {
    u32 s = (u32)__cvta_generic_to_shared(smem);
    asm volatile("cp.async.cg.shared.global [%0], [%1], 16, %2;"
                 :: "r"(s), "l"(g), "r"(0u));
}
__device__ __forceinline__ void cpa_commit() {
    asm volatile("cp.async.commit_group;" ::: "memory");
}
template<int N> __device__ __forceinline__ void cpa_wait() {
    asm volatile("cp.async.wait_group %0;" :: "n"(N) : "memory");
}
__device__ __forceinline__ float4 bnrelu4(float4 v, float4 sc, float4 sh) {
    v.x = fmaxf(fmaf(v.x, sc.x, sh.x), 0.f);
    v.y = fmaxf(fmaf(v.y, sc.y, sh.y), 0.f);
    v.z = fmaxf(fmaf(v.z, sc.z, sh.z), 0.f);
    v.w = fmaxf(fmaf(v.w, sc.w, sh.w), 0.f);
    return v;
}
__device__ __forceinline__ float4 unpack_h4(uint2 u) {
    float2 f0 = __half22float2(*reinterpret_cast<__half2*>(&u.x));
    float2 f1 = __half22float2(*reinterpret_cast<__half2*>(&u.y));
    return make_float4(f0.x, f0.y, f1.x, f1.y);
}
__device__ __forceinline__ uint2 pack_h4(float4 v) {
    __half2 p0 = __floats2half2_rn(v.x, v.y);
    __half2 p1 = __floats2half2_rn(v.z, v.w);
    uint2 o;
    o.x = *reinterpret_cast<u32*>(&p0);
    o.y = *reinterpret_cast<u32*>(&p1);
    return o;
}

// ---------------------------------------------------------------------------
// prep: dtype detect, fp16 frag-ordered weights, zero cnt/BN, x -> fp16.
__global__ void __launch_bounds__(256) prep_all(
    const float* __restrict__ x, const void* __restrict__ ei,
    const float* __restrict__ w1l, const float* __restrict__ w1r,
    const float* __restrict__ w2l, const float* __restrict__ w2r, int Nn)
{
    int t = blockIdx.x * blockDim.x + threadIdx.x;
    int stride = gridDim.x * blockDim.x;
    if (blockIdx.x == 0 && threadIdx.x < 32) {
        int lane = threadIdx.x;
        long long v = ((const long long*)ei)[lane & 15];
        unsigned bad = __ballot_sync(0xffffffffu, v < 0 || v >= (long long)Nn);
        if (lane == 0) g_ei32 = bad ? 1 : 0;
    }
    for (int w = t; w < 16384; w += stride) {
        int kk = w >> 10;
        int r = w & 1023;
        int nb = r >> 6;
        int r2 = r & 63;
        int hs = r2 >> 5;
        int r3 = r2 & 31;
        int cib = r3 >> 2;
        int tt = r3 & 3;
        int col = nb * 8 + cib;
        int k0 = kk * 16 + 2 * tt + hs * 8;
        float v0 = (k0 < 128) ? w1l[col * 128 + k0] : w1r[col * 128 + k0 - 128];
        int k1 = k0 + 1;
        float v1 = (k1 < 128) ? w1l[col * 128 + k1] : w1r[col * 128 + k1 - 128];
        __half2 h = __floats2half2_rn(v0, v1);
        int dest = (kk >> 1) * 2048 + (kk & 1) * 1024 + nb * 64 + hs * 32 + cib * 4 + tt;
        g_wT1h[dest] = *reinterpret_cast<u32*>(&h);
    }
    for (int w = t; w < 6144; w += stride) {
        int kk = w / 384;
        int r = w - kk * 384;
        int nb = r >> 6;
        int r2 = r & 63;
        int hs = r2 >> 5;
        int r3 = r2 & 31;
        int cib = r3 >> 2;
        int tt = r3 & 3;
        int col = nb * 8 + cib;
        int k0 = kk * 16 + 2 * tt + hs * 8;
        float v0 = 0.f, v1 = 0.f;
        if (col < 47) {
            v0 = (k0 < 128) ? w2l[col * 128 + k0] : w2r[col * 128 + k0 - 128];
            v1 = (k0 + 1 < 128) ? w2l[col * 128 + k0 + 1] : w2r[col * 128 + k0 + 1 - 128];
        }
        __half2 h = __floats2half2_rn(v0, v1);
        int dest = (kk >> 1) * 768 + (kk & 1) * 384 + nb * 64 + hs * 32 + cib * 4 + tt;
        g_wT2h[dest] = *reinterpret_cast<u32*>(&h);
    }
    for (int j = t; j < Nn; j += stride) g_cnt[j] = 0;
    if (t < 128) { g_bnsum[t] = 0.f; g_bnsq[t] = 0.f; }
    // x -> fp16
    const float4* x4 = (const float4*)x;
    uint2* out = (uint2*)g_x16;
    int n4 = Nn * 32;
    for (int j = t; j < n4; j += stride) out[j] = pack_h4(x4[j]);
}

__global__ void __launch_bounds__(256) build_adj(
    const void* __restrict__ ei, int E, int Nn)
{
    const int is32 = g_ei32;
    int t = blockIdx.x * blockDim.x + threadIdx.x;
    int stride = gridDim.x * blockDim.x;
    for (int e = t; e < E; e += stride) {
        int src, dst;
        if (is32) {
            src = ((const int*)ei)[e];
            dst = ((const int*)ei)[(size_t)E + e];
        } else {
            src = (int)((const long long*)ei)[e];
            dst = (int)((const long long*)ei)[(size_t)E + e];
        }
        if ((unsigned)src >= (unsigned)Nn || (unsigned)dst >= (unsigned)Nn) continue;
        int pos = atomicAdd(&g_cnt[dst], 1);
        if (pos < SLOTS) g_slot[(size_t)dst * SLOTS + pos] = src;
    }
}

// Gather: one warp per node; lane owns channels 4l..4l+3.
// srcSel: 0 -> g_x16 (layer 1), 1 -> g_h16 with BN+ReLU (layer 2).
__global__ void __launch_bounds__(256, 6) gather_mean(int srcSel, int Nn)
{
    const uint2* feat2 = srcSel ? (const uint2*)g_h16 : (const uint2*)g_x16;
    const int withBN = srcSel;
    int gw   = (blockIdx.x * blockDim.x + threadIdx.x) >> 5;
    int lane = threadIdx.x & 31;
    int nw   = (gridDim.x * blockDim.x) >> 5;
    float4 sc = make_float4(1.f, 1.f, 1.f, 1.f);
    float4 sh = make_float4(0.f, 0.f, 0.f, 0.f);
    if (withBN) {
        sc = ((const float4*)g_bnscale)[lane];
        sh = ((const float4*)g_bnshift)[lane];
    }
    uint2* out2 = (uint2*)g_in16;
    for (int n = gw; n < Nn; n += nw) {
        int cnt = g_cnt[n];
        int m = min(cnt, SLOTS);
        const int* sl = g_slot + (size_t)n * SLOTS;
        float4 a = make_float4(0.f, 0.f, 0.f, 0.f);
        int j = 0;
        for (; j + 4 <= m; j += 4) {
            float4 v0 = unpack_h4(feat2[(size_t)sl[j]     * 32 + lane]);
            float4 v1 = unpack_h4(feat2[(size_t)sl[j + 1] * 32 + lane]);
            float4 v2 = unpack_h4(feat2[(size_t)sl[j + 2] * 32 + lane]);
            float4 v3 = unpack_h4(feat2[(size_t)sl[j + 3] * 32 + lane]);
            if (withBN) {
                v0 = bnrelu4(v0, sc, sh); v1 = bnrelu4(v1, sc, sh);
                v2 = bnrelu4(v2, sc, sh); v3 = bnrelu4(v3, sc, sh);
            }
            a.x += (v0.x + v1.x) + (v2.x + v3.x);
            a.y += (v0.y + v1.y) + (v2.y + v3.y);
            a.z += (v0.z + v1.z) + (v2.z + v3.z);
            a.w += (v0.w + v1.w) + (v2.w + v3.w);
        }
        for (; j < m; j++) {
            float4 v = unpack_h4(feat2[(size_t)sl[j] * 32 + lane]);
            if (withBN) v = bnrelu4(v, sc, sh);
            a.x += v.x; a.y += v.y; a.z += v.z; a.w += v.w;
        }
        float r = 1.f / fmaxf((float)cnt, 1.f);
        a.x *= r; a.y *= r; a.z *= r; a.w *= r;
        out2[(size_t)n * 64 + lane] = pack_h4(a);
        float4 s = unpack_h4(feat2[(size_t)n * 32 + lane]);
        if (withBN) s = bnrelu4(s, sc, sh);
        out2[(size_t)n * 64 + 32 + lane] = pack_h4(s);
    }
}

// ---------------------------------------------------------------------------
// GEMM1 (fp16 mma m16n8k16, 2-stage cp.async): h = L2norm_row(g_in @ W1 + b1l)
// 256 threads = 8 warps (wm 0..3, wn 0..1); 128-node x 128-ch tile.
// dyn smem: wS 2x2048 + inS 2x2560 words = 36864 B.
// ---------------------------------------------------------------------------
__global__ void __launch_bounds__(256) sage_gemm1(
    const float* __restrict__ bias, int Nn)
{
    extern __shared__ u32 dyn[];
    u32* wSb = dyn;            // 2 * 2048
    u32* iSb = dyn + 4096;     // 2 * 2560
    __shared__ float ssS[2][128];
    __shared__ float bnstage[2][8][128];

    const int tid  = threadIdx.x;
    const int warp = tid >> 5, lane = tid & 31;
    const int wm = warp >> 1, wn = warp & 1;
    const int qr = lane >> 2, qk = lane & 3;

    float2 bp[8];
#pragma unroll
    for (int nb = 0; nb < 8; nb++)
        bp[nb] = *(const float2*)&bias[wn * 64 + nb * 8 + 2 * qk];

    float2 s1[8], s2[8];
#pragma unroll
    for (int nb = 0; nb < 8; nb++) { s1[nb] = make_float2(0.f, 0.f); s2[nb] = make_float2(0.f, 0.f); }

    for (int base = blockIdx.x * 128; base < Nn; base += gridDim.x * 128) {
        int nrem = min(128, Nn - base);

        float acc[2][8][4];
#pragma unroll
        for (int mb = 0; mb < 2; mb++)
#pragma unroll
            for (int nb = 0; nb < 8; nb++)
#pragma unroll
                for (int q = 0; q < 4; q++) acc[mb][nb][q] = 0.f;

        auto stage = [&](int kc, int buf) {
            u32* wdst = wSb + buf * 2048;
            const u32* wsrc = g_wT1h + kc * 2048;
            for (int i4 = tid; i4 < 512; i4 += 256) cpa16(&wdst[i4 * 4], &wsrc[i4 * 4]);
            u32* ib = iSb + buf * 2560;
            for (int i = tid; i < 512; i += 256) {
                int n = i >> 2, q = i & 3;
                void* dst = &ib[n * IWSTR + q * 4];
                const void* src = &g_in16[(size_t)(base + n) * 128 + kc * 16 + q * 4];
                if (n < nrem) cpa16(dst, src);
                else          cpa16_zero(dst, g_in16);
            }
        };

        stage(0, 0);
        cpa_commit();
        for (int kc = 0; kc < 8; kc++) {
            int cur = kc & 1;
            if (kc < 7) { stage(kc + 1, cur ^ 1); cpa_commit(); cpa_wait<1>(); }
            else        { cpa_wait<0>(); }
            __syncthreads();

            const u32* wS = wSb + cur * 2048;
            const u32* inS = iSb + cur * 2560;
#pragma unroll
            for (int ks = 0; ks < 2; ks++) {
                u32 b0[8], b1[8];
                int wb0 = ks * 1024 + wn * 512 + qr * 4 + qk;
#pragma unroll
                for (int nb = 0; nb < 8; nb++) {
                    b0[nb] = wS[wb0 + nb * 64];
                    b1[nb] = wS[wb0 + nb * 64 + 32];
                }
                u32 a[2][4];
#pragma unroll
                for (int mb = 0; mb < 2; mb++) {
                    int r0 = (wm * 32 + mb * 16 + qr) * IWSTR + ks * 8 + qk;
                    int r1 = r0 + 8 * IWSTR;
                    a[mb][0] = inS[r0];
                    a[mb][1] = inS[r1];
                    a[mb][2] = inS[r0 + 4];
                    a[mb][3] = inS[r1 + 4];
                }
#pragma unroll
                for (int mb = 0; mb < 2; mb++)
#pragma unroll
                    for (int nb = 0; nb < 8; nb++)
                        mma_f16(acc[mb][nb], a[mb][0], a[mb][1], a[mb][2], a[mb][3],
                                b0[nb], b1[nb]);
            }
            __syncthreads();
        }

        // Epilogue: bias, row L2 norm, store h (fp16), BN partials (fp32)
        float ssp[2][2] = {{0.f, 0.f}, {0.f, 0.f}};
#pragma unroll
        for (int mb = 0; mb < 2; mb++)
#pragma unroll
            for (int nb = 0; nb < 8; nb++) {
                acc[mb][nb][0] += bp[nb].x; acc[mb][nb][1] += bp[nb].y;
                acc[mb][nb][2] += bp[nb].x; acc[mb][nb][3] += bp[nb].y;
                ssp[mb][0] += acc[mb][nb][0] * acc[mb][nb][0] + acc[mb][nb][1] * acc[mb][nb][1];
                ssp[mb][1] += acc[mb][nb][2] * acc[mb][nb][2] + acc[mb][nb][3] * acc[mb][nb][3];
            }
#pragma unroll
        for (int mb = 0; mb < 2; mb++)
#pragma unroll
            for (int rs = 0; rs < 2; rs++) {
                ssp[mb][rs] += __shfl_xor_sync(0xffffffffu, ssp[mb][rs], 1);
                ssp[mb][rs] += __shfl_xor_sync(0xffffffffu, ssp[mb][rs], 2);
            }
        if (qk == 0) {
#pragma unroll
            for (int mb = 0; mb < 2; mb++)
#pragma unroll
                for (int rs = 0; rs < 2; rs++)
                    ssS[wn][wm * 32 + mb * 16 + rs * 8 + qr] = ssp[mb][rs];
        }
        __syncthreads();
        float inv[2][2];
#pragma unroll
        for (int mb = 0; mb < 2; mb++)
#pragma unroll
            for (int rs = 0; rs < 2; rs++) {
                int lr = wm * 32 + mb * 16 + rs * 8 + qr;
                float tot = ssS[0][lr] + ssS[1][lr];
                inv[mb][rs] = 1.f / fmaxf(sqrtf(tot), 1e-12f);
            }
#pragma unroll
        for (int mb = 0; mb < 2; mb++) {
            int lr0 = wm * 32 + mb * 16 + qr;
            int lr1 = lr0 + 8;
#pragma unroll
            for (int nb = 0; nb < 8; nb++) {
                int word = wn * 32 + nb * 4 + qk;
                if (lr0 < nrem) {
                    float vx = acc[mb][nb][0] * inv[mb][0];
                    float vy = acc[mb][nb][1] * inv[mb][0];
                    __half2 hv = __floats2half2_rn(vx, vy);
                    g_h16[(size_t)(base + lr0) * 64 + word] = *reinterpret_cast<u32*>(&hv);
                    s1[nb].x += vx; s1[nb].y += vy;
                    s2[nb].x += vx * vx; s2[nb].y += vy * vy;
                }
                if (lr1 < nrem) {
                    float vx = acc[mb][nb][2] * inv[mb][1];
                    float vy = acc[mb][nb][3] * inv[mb][1];
                    __half2 hv = __floats2half2_rn(vx, vy);
                    g_h16[(size_t)(base + lr1) * 64 + word] = *reinterpret_cast<u32*>(&hv);
                    s1[nb].x += vx; s1[nb].y += vy;
                    s2[nb].x += vx * vx; s2[nb].y += vy * vy;
                }
            }
        }
        __syncthreads();
    }

    // BN reduction: shuffle over qr, stage per warp, combine 4 warps per wn.
#pragma unroll
    for (int off = 4; off < 32; off <<= 1) {
#pragma unroll
        for (int nb = 0; nb < 8; nb++) {
            s1[nb].x += __shfl_xor_sync(0xffffffffu, s1[nb].x, off);
            s1[nb].y += __shfl_xor_sync(0xffffffffu, s1[nb].y, off);
            s2[nb].x += __shfl_xor_sync(0xffffffffu, s2[nb].x, off);
            s2[nb].y += __shfl_xor_sync(0xffffffffu, s2[nb].y, off);
        }
    }
    if (lane < 4) {
#pragma unroll
        for (int nb = 0; nb < 8; nb++) {
            int c = wn * 64 + nb * 8 + 2 * lane;
            bnstage[0][warp][c] = s1[nb].x; bnstage[0][warp][c + 1] = s1[nb].y;
            bnstage[1][warp][c] = s2[nb].x; bnstage[1][warp][c + 1] = s2[nb].y;
        }
    }
    __syncthreads();
    if (tid < 128) {
        int wsel = tid >> 6;   // wn owning this channel
        float a0 = bnstage[0][wsel][tid]     + bnstage[0][2 + wsel][tid]
                 + bnstage[0][4 + wsel][tid] + bnstage[0][6 + wsel][tid];
        float a1 = bnstage[1][wsel][tid]     + bnstage[1][2 + wsel][tid]
                 + bnstage[1][4 + wsel][tid] + bnstage[1][6 + wsel][tid];
        atomicAdd(&g_bnsum[tid], a0);
        atomicAdd(&g_bnsq[tid], a1);
    }
}

__global__ void bn_finalize(const float* __restrict__ gamma, const float* __restrict__ beta, float invN) {
    int c = threadIdx.x;
    float mean = g_bnsum[c] * invN;
    float var = g_bnsq[c] * invN - mean * mean;
    float sc = gamma[c] * rsqrtf(var + 1e-5f);
    g_bnscale[c] = sc;
    g_bnshift[c] = beta[c] - mean * sc;
}

// ---------------------------------------------------------------------------
// GEMM2 (fp16 mma, 2-stage): out = L2norm_row(g_in @ W2 + b2l)
// 256 threads, 128-node tile; cols 48 (padded), 47 written.
// ---------------------------------------------------------------------------
__global__ void __launch_bounds__(256) sage_gemm2(
    const float* __restrict__ b2l, float* __restrict__ outp, int Nn)
{
    extern __shared__ u32 dyn[];
    u32* wSb = dyn;            // 2 * 768
    u32* iSb = dyn + 1536;     // 2 * 2560
    __shared__ float ssS[2][128];

    const int tid  = threadIdx.x;
    const int warp = tid >> 5, lane = tid & 31;
    const int wm = warp >> 1, wn = warp & 1;
    const int qr = lane >> 2, qk = lane & 3;

    float2 bp[3];
#pragma unroll
    for (int nb = 0; nb < 3; nb++) {
        int c = wn * 24 + nb * 8 + 2 * qk;
        bp[nb].x = (c < 47) ? b2l[c] : 0.f;
        bp[nb].y = (c + 1 < 47) ? b2l[c + 1] : 0.f;
    }

    for (int base = blockIdx.x * 128; base < Nn; base += gridDim.x * 128) {
        int nrem = min(128, Nn - base);

        float acc[2][3][4];
#pragma unroll
        for (int mb = 0; mb < 2; mb++)
#pragma unroll
            for (int nb = 0; nb < 3; nb++)
#pragma unroll
                for (int q = 0; q < 4; q++) acc[mb][nb][q] = 0.f;

        auto stage = [&](int kc, int buf) {
            u32* wdst = wSb + buf * 768;
            const u32* wsrc = g_wT2h + kc * 768;
            for (int i4 = tid; i4 < 192; i4 += 256) cpa16(&wdst[i4 * 4], &wsrc[i4 * 4]);
            u32* ib = iSb + buf * 2560;
            for (int i = tid; i < 512; i += 256) {
                int n = i >> 2, q = i & 3;
                void* dst = &ib[n * IWSTR + q * 4];
                const void* src = &g_in16[(size_t)(base + n) * 128 + kc * 16 + q * 4];
                if (n < nrem) cpa16(dst, src);
                else          cpa16_zero(dst, g_in16);
            }
        };

        stage(0, 0);
        cpa_commit();
        for (int kc = 0; kc < 8; kc++) {
            int cur = kc & 1;
            if (kc < 7) { stage(kc + 1, cur ^ 1); cpa_commit(); cpa_wait<1>(); }
            else        { cpa_wait<0>(); }
            __syncthreads();

            const u32* wS = wSb + cur * 768;
            const u32* inS = iSb + cur * 2560;
#pragma unroll
            for (int ks = 0; ks < 2; ks++) {
                u32 b0[3], b1[3];
                int wb0 = ks * 384 + wn * 192 + qr * 4 + qk;
#pragma unroll
                for (int nb = 0; nb < 3; nb++) {
                    b0[nb] = wS[wb0 + nb * 64];
                    b1[nb] = wS[wb0 + nb * 64 + 32];
                }
                u32 a[2][4];
#pragma unroll
                for (int mb = 0; mb < 2; mb++) {
                    int r0 = (wm * 32 + mb * 16 + qr) * IWSTR + ks * 8 + qk;
                    int r1 = r0 + 8 * IWSTR;
                    a[mb][0] = inS[r0];
                    a[mb][1] = inS[r1];
                    a[mb][2] = inS[r0 + 4];
                    a[mb][3] = inS[r1 + 4];
                }
#pragma unroll
                for (int mb = 0; mb < 2; mb++)
#pragma unroll
                    for (int nb = 0; nb < 3; nb++)
                        mma_f16(acc[mb][nb], a[mb][0], a[mb][1], a[mb][2], a[mb][3],
                                b0[nb], b1[nb]);
            }
            __syncthreads();
        }

        float ssp[2][2] = {{0.f, 0.f}, {0.f, 0.f}};
#pragma unroll
        for (int mb = 0; mb < 2; mb++)
#pragma unroll
            for (int nb = 0; nb < 3; nb++) {
                acc[mb][nb][0] += bp[nb].x; acc[mb][nb][1] += bp[nb].y;
                acc[mb][nb][2] += bp[nb].x; acc[mb][nb][3] += bp[nb].y;
                ssp[mb][0] += acc[mb][nb][0] * acc[mb][nb][0] + acc[mb][nb][1] * acc[mb][nb][1];
                ssp[mb][1] += acc[mb][nb][2] * acc[mb][nb][2] + acc[mb][nb][3] * acc[mb][nb][3];
            }
#pragma unroll
        for (int mb = 0; mb < 2; mb++)
#pragma unroll
            for (int rs = 0; rs < 2; rs++) {
                ssp[mb][rs] += __shfl_xor_sync(0xffffffffu, ssp[mb][rs], 1);
                ssp[mb][rs] += __shfl_xor_sync(0xffffffffu, ssp[mb][rs], 2);
            }
        if (qk == 0) {
#pragma unroll
            for (int mb = 0; mb < 2; mb++)
#pragma unroll
                for (int rs = 0; rs < 2; rs++)
                    ssS[wn][wm * 32 + mb * 16 + rs * 8 + qr] = ssp[mb][rs];
        }
        __syncthreads();
        float inv[2][2];
#pragma unroll
        for (int mb = 0; mb < 2; mb++)
#pragma unroll
            for (int rs = 0; rs < 2; rs++) {
                int lr = wm * 32 + mb * 16 + rs * 8 + qr;
                float tot = ssS[0][lr] + ssS[1][lr];
                inv[mb][rs] = 1.f / fmaxf(sqrtf(tot), 1e-12f);
            }
#pragma unroll
        for (int mb = 0; mb < 2; mb++) {
            int lr0 = wm * 32 + mb * 16 + qr;
            int lr1 = lr0 + 8;
#pragma unroll
            for (int nb = 0; nb < 3; nb++) {
                int c0 = wn * 24 + nb * 8 + 2 * qk;
                if (lr0 < nrem) {
                    size_t o = (size_t)(base + lr0) * 47;
                    if (c0 < 47)     outp[o + c0]     = acc[mb][nb][0] * inv[mb][0];
                    if (c0 + 1 < 47) outp[o + c0 + 1] = acc[mb][nb][1] * inv[mb][0];
                }
                if (lr1 < nrem) {
                    size_t o = (size_t)(base + lr1) * 47;
                    if (c0 < 47)     outp[o + c0]     = acc[mb][nb][2] * inv[mb][1];
                    if (c0 + 1 < 47) outp[o + c0 + 1] = acc[mb][nb][3] * inv[mb][1];
                }
            }
        }
        __syncthreads();
    }
}

// ---------------------------------------------------------------------------
extern "C" void kernel_launch(void* const* d_in, const int* in_sizes, int n_in,
                              void* d_out, int out_size) {
    const float* x     = (const float*)d_in[0];
    const void*  ei    = d_in[1];
    const float* w1l   = (const float*)d_in[2];
    const float* b1l   = (const float*)d_in[3];
    const float* w1r   = (const float*)d_in[4];
    const float* gamma = (const float*)d_in[5];
    const float* beta  = (const float*)d_in[6];
    const float* w2l   = (const float*)d_in[7];
    const float* b2l   = (const float*)d_in[8];
    const float* w2r   = (const float*)d_in[9];
    int Nn = in_sizes[0] / 128;
    int E  = in_sizes[1] / 2;

    int gb = (Nn + 127) / 128;
    int smem1 = (2 * 2048 + 2 * 2560) * 4;   // 36864 B
    int smem2 = (2 * 768 + 2 * 2560) * 4;    // 26624 B

    prep_all<<<1024, 256>>>(x, ei, w1l, w1r, w2l, w2r, Nn);
    build_adj<<<(E + 255) / 256, 256>>>(ei, E, Nn);
    gather_mean<<<2048, 256>>>(0, Nn);
    sage_gemm1<<<gb, 256, smem1>>>(b1l, Nn);
    bn_finalize<<<1, 128>>>(gamma, beta, 1.0f / (float)Nn);
    gather_mean<<<2048, 256>>>(1, Nn);
    sage_gemm2<<<gb, 256, smem2>>>(b2l, (float*)d_out, Nn);
}

// round 15
// speedup vs baseline: 1.1077x; 1.1077x over previous
#include <cuda_runtime.h>
#include <cuda_fp16.h>
#include <cstdint>
#include <cstddef>

// ---------------------------------------------------------------------------
// GraphSAGE 2-layer (N=100000, E=800000, 128 -> 128 -> 47, fp32 in/out):
//   prep(dtype+weights+zero+x->fp16) -> adjacency build ->
//   gather([agg|self] fp16) -> GEMM1(fp16 mma, 128-thread/64-node tiles,
//   2-stage cp.async, +bias+L2norm+BN) -> BN finalize -> gather(+BN+ReLU) ->
//   GEMM2(fp16 mma) -> out
// GEMM blocks stay at 128 threads: co-resident CTAs are the latency hiding
// (256-thread tiles -> 164 regs -> 1 CTA/SM -> R14 regression).
// Device-global pointers always selected INSIDE kernels (GB300 ATS trap).
// ---------------------------------------------------------------------------

#define NMAX 100000
#define IWSTR 20         // inS row stride in u32 words (40 halves)
#define SLOTS 64

typedef unsigned long long u64;
typedef unsigned int u32;

__device__ __align__(16) u32  g_x16[(size_t)NMAX * 64];    // x as fp16
__device__ __align__(16) u32  g_h16[(size_t)NMAX * 64];    // h as fp16
__device__ __align__(16) u32  g_in16[(size_t)NMAX * 128];  // [agg|self] fp16
__device__ __align__(16) int  g_cnt[NMAX];
__device__ __align__(16) int  g_slot[(size_t)NMAX * SLOTS];
__device__ __align__(16) u32  g_wT1h[16384];  // fp16 frag-ordered
__device__ __align__(16) u32  g_wT2h[6144];
__device__ __align__(16) float g_bnsum[128];
__device__ __align__(16) float g_bnsq[128];
__device__ __align__(16) float g_bnscale[128];
__device__ __align__(16) float g_bnshift[128];
__device__ int g_ei32;

// ---- helpers ---------------------------------------------------------------
__device__ __forceinline__ void mma_f16(float* c, u32 a0, u32 a1, u32 a2, u32 a3,
                                        u32 b0, u32 b1) {
    asm volatile(
        "mma.sync.aligned.m16n8k16.row.col.f32.f16.f16.f32 "
        "{%0,%1,%2,%3}, {%4,%5,%6,%7}, {%8,%9}, {%0,%1,%2,%3};"
        : "+f"(c[0]), "+f"(c[1]), "+f"(c[2]), "+f"(c[3])
        : "r"(a0), "r"(a1), "r"(a2), "r"(a3), "r"(b0), "r"(b1));
}
__device__ __forceinline__ void cpa16(void* smem, const void* g) {
    u32 s = (u32)__cvta_generic_to_shared(smem);
    asm volatile("cp.async.cg.shared.global [%0], [%1], 16;" :: "r"(s), "l"(g));
}
__device__ __forceinline__ void cpa16_zero(void* smem, const void* g) {
    u32 s = (u32)__cvta_generic_to_shared(smem);
    asm volatile("cp.async.cg.shared.global [%0], [%1], 16, %2;"
                 :: "r"(s), "l"(g), "r"(0u));
}
__device__ __forceinline__ void cpa_commit() {
    asm volatile("cp.async.commit_group;" ::: "memory");
}
template<int N> __device__ __forceinline__ void cpa_wait() {
    asm volatile("cp.async.wait_group %0;" :: "n"(N) : "memory");
}
__device__ __forceinline__ float4 bnrelu4(float4 v, float4 sc, float4 sh) {
    v.x = fmaxf(fmaf(v.x, sc.x, sh.x), 0.f);
    v.y = fmaxf(fmaf(v.y, sc.y, sh.y), 0.f);
    v.z = fmaxf(fmaf(v.z, sc.z, sh.z), 0.f);
    v.w = fmaxf(fmaf(v.w, sc.w, sh.w), 0.f);
    return v;
}
__device__ __forceinline__ float4 unpack_h4(uint2 u) {
    float2 f0 = __half22float2(*reinterpret_cast<__half2*>(&u.x));
    float2 f1 = __half22float2(*reinterpret_cast<__half2*>(&u.y));
    return make_float4(f0.x, f0.y, f1.x, f1.y);
}
__device__ __forceinline__ uint2 pack_h4(float4 v) {
    __half2 p0 = __floats2half2_rn(v.x, v.y);
    __half2 p1 = __floats2half2_rn(v.z, v.w);
    uint2 o;
    o.x = *reinterpret_cast<u32*>(&p0);
    o.y = *reinterpret_cast<u32*>(&p1);
    return o;
}

// ---------------------------------------------------------------------------
// prep: dtype detect, fp16 frag-ordered weights, zero cnt/BN, x -> fp16.
__global__ void __launch_bounds__(256) prep_all(
    const float* __restrict__ x, const void* __restrict__ ei,
    const float* __restrict__ w1l, const float* __restrict__ w1r,
    const float* __restrict__ w2l, const float* __restrict__ w2r, int Nn)
{
    int t = blockIdx.x * blockDim.x + threadIdx.x;
    int stride = gridDim.x * blockDim.x;
    if (blockIdx.x == 0 && threadIdx.x < 32) {
        int lane = threadIdx.x;
        long long v = ((const long long*)ei)[lane & 15];
        unsigned bad = __ballot_sync(0xffffffffu, v < 0 || v >= (long long)Nn);
        if (lane == 0) g_ei32 = bad ? 1 : 0;
    }
    for (int w = t; w < 16384; w += stride) {
        int kk = w >> 10;
        int r = w & 1023;
        int nb = r >> 6;
        int r2 = r & 63;
        int hs = r2 >> 5;
        int r3 = r2 & 31;
        int cib = r3 >> 2;
        int tt = r3 & 3;
        int col = nb * 8 + cib;
        int k0 = kk * 16 + 2 * tt + hs * 8;
        float v0 = (k0 < 128) ? w1l[col * 128 + k0] : w1r[col * 128 + k0 - 128];
        int k1 = k0 + 1;
        float v1 = (k1 < 128) ? w1l[col * 128 + k1] : w1r[col * 128 + k1 - 128];
        __half2 h = __floats2half2_rn(v0, v1);
        int dest = (kk >> 1) * 2048 + (kk & 1) * 1024 + nb * 64 + hs * 32 + cib * 4 + tt;
        g_wT1h[dest] = *reinterpret_cast<u32*>(&h);
    }
    for (int w = t; w < 6144; w += stride) {
        int kk = w / 384;
        int r = w - kk * 384;
        int nb = r >> 6;
        int r2 = r & 63;
        int hs = r2 >> 5;
        int r3 = r2 & 31;
        int cib = r3 >> 2;
        int tt = r3 & 3;
        int col = nb * 8 + cib;
        int k0 = kk * 16 + 2 * tt + hs * 8;
        float v0 = 0.f, v1 = 0.f;
        if (col < 47) {
            v0 = (k0 < 128) ? w2l[col * 128 + k0] : w2r[col * 128 + k0 - 128];
            v1 = (k0 + 1 < 128) ? w2l[col * 128 + k0 + 1] : w2r[col * 128 + k0 + 1 - 128];
        }
        __half2 h = __floats2half2_rn(v0, v1);
        int dest = (kk >> 1) * 768 + (kk & 1) * 384 + nb * 64 + hs * 32 + cib * 4 + tt;
        g_wT2h[dest] = *reinterpret_cast<u32*>(&h);
    }
    for (int j = t; j < Nn; j += stride) g_cnt[j] = 0;
    if (t < 128) { g_bnsum[t] = 0.f; g_bnsq[t] = 0.f; }
    const float4* x4 = (const float4*)x;
    uint2* out = (uint2*)g_x16;
    int n4 = Nn * 32;
    for (int j = t; j < n4; j += stride) out[j] = pack_h4(x4[j]);
}

__global__ void __launch_bounds__(256) build_adj(
    const void* __restrict__ ei, int E, int Nn)
{
    const int is32 = g_ei32;
    int t = blockIdx.x * blockDim.x + threadIdx.x;
    int stride = gridDim.x * blockDim.x;
    for (int e = t; e < E; e += stride) {
        int src, dst;
        if (is32) {
            src = ((const int*)ei)[e];
            dst = ((const int*)ei)[(size_t)E + e];
        } else {
            src = (int)((const long long*)ei)[e];
            dst = (int)((const long long*)ei)[(size_t)E + e];
        }
        if ((unsigned)src >= (unsigned)Nn || (unsigned)dst >= (unsigned)Nn) continue;
        int pos = atomicAdd(&g_cnt[dst], 1);
        if (pos < SLOTS) g_slot[(size_t)dst * SLOTS + pos] = src;
    }
}

// Gather: one warp per node; lane owns channels 4l..4l+3.
// srcSel: 0 -> g_x16 (layer 1), 1 -> g_h16 with BN+ReLU (layer 2).
__global__ void __launch_bounds__(256, 6) gather_mean(int srcSel, int Nn)
{
    const uint2* feat2 = srcSel ? (const uint2*)g_h16 : (const uint2*)g_x16;
    const int withBN = srcSel;
    int gw   = (blockIdx.x * blockDim.x + threadIdx.x) >> 5;
    int lane = threadIdx.x & 31;
    int nw   = (gridDim.x * blockDim.x) >> 5;
    float4 sc = make_float4(1.f, 1.f, 1.f, 1.f);
    float4 sh = make_float4(0.f, 0.f, 0.f, 0.f);
    if (withBN) {
        sc = ((const float4*)g_bnscale)[lane];
        sh = ((const float4*)g_bnshift)[lane];
    }
    uint2* out2 = (uint2*)g_in16;
    for (int n = gw; n < Nn; n += nw) {
        int cnt = g_cnt[n];
        int m = min(cnt, SLOTS);
        const int* sl = g_slot + (size_t)n * SLOTS;
        float4 a = make_float4(0.f, 0.f, 0.f, 0.f);
        int j = 0;
        for (; j + 4 <= m; j += 4) {
            float4 v0 = unpack_h4(feat2[(size_t)sl[j]     * 32 + lane]);
            float4 v1 = unpack_h4(feat2[(size_t)sl[j + 1] * 32 + lane]);
            float4 v2 = unpack_h4(feat2[(size_t)sl[j + 2] * 32 + lane]);
            float4 v3 = unpack_h4(feat2[(size_t)sl[j + 3] * 32 + lane]);
            if (withBN) {
                v0 = bnrelu4(v0, sc, sh); v1 = bnrelu4(v1, sc, sh);
                v2 = bnrelu4(v2, sc, sh); v3 = bnrelu4(v3, sc, sh);
            }
            a.x += (v0.x + v1.x) + (v2.x + v3.x);
            a.y += (v0.y + v1.y) + (v2.y + v3.y);
            a.z += (v0.z + v1.z) + (v2.z + v3.z);
            a.w += (v0.w + v1.w) + (v2.w + v3.w);
        }
        for (; j < m; j++) {
            float4 v = unpack_h4(feat2[(size_t)sl[j] * 32 + lane]);
            if (withBN) v = bnrelu4(v, sc, sh);
            a.x += v.x; a.y += v.y; a.z += v.z; a.w += v.w;
        }
        float r = 1.f / fmaxf((float)cnt, 1.f);
        a.x *= r; a.y *= r; a.z *= r; a.w *= r;
        out2[(size_t)n * 64 + lane] = pack_h4(a);
        float4 s = unpack_h4(feat2[(size_t)n * 32 + lane]);
        if (withBN) s = bnrelu4(s, sc, sh);
        out2[(size_t)n * 64 + 32 + lane] = pack_h4(s);
    }
}

// ---------------------------------------------------------------------------
// GEMM1 (fp16 mma m16n8k16, 2-stage cp.async): h = L2norm_row(g_in @ W1 + b1l)
// 128 threads = 4 warps (wm,wn 2x2); 64-node x 128-ch tile.
// ---------------------------------------------------------------------------
__global__ void __launch_bounds__(128) sage_gemm1(
    const float* __restrict__ bias, int Nn)
{
    extern __shared__ u32 dyn[];
    u32* wSb = dyn;            // 2 * 2048
    u32* iSb = dyn + 4096;     // 2 * 1280
    __shared__ float ssS[2][64];
    __shared__ float bnstage[2][4][128];

    const int tid  = threadIdx.x;
    const int warp = tid >> 5, lane = tid & 31;
    const int wm = warp >> 1, wn = warp & 1;
    const int qr = lane >> 2, qk = lane & 3;

    float2 bp[8];
#pragma unroll
    for (int nb = 0; nb < 8; nb++)
        bp[nb] = *(const float2*)&bias[wn * 64 + nb * 8 + 2 * qk];

    float2 s1[8], s2[8];
#pragma unroll
    for (int nb = 0; nb < 8; nb++) { s1[nb] = make_float2(0.f, 0.f); s2[nb] = make_float2(0.f, 0.f); }

    for (int base = blockIdx.x * 64; base < Nn; base += gridDim.x * 64) {
        int nrem = min(64, Nn - base);

        float acc[2][8][4];
#pragma unroll
        for (int mb = 0; mb < 2; mb++)
#pragma unroll
            for (int nb = 0; nb < 8; nb++)
#pragma unroll
                for (int q = 0; q < 4; q++) acc[mb][nb][q] = 0.f;

        auto stage = [&](int kc, int buf) {
            u32* wdst = wSb + buf * 2048;
            const u32* wsrc = g_wT1h + kc * 2048;
            for (int i4 = tid; i4 < 512; i4 += 128) cpa16(&wdst[i4 * 4], &wsrc[i4 * 4]);
            u32* ib = iSb + buf * 1280;
            for (int i = tid; i < 256; i += 128) {
                int n = i >> 2, q = i & 3;
                void* dst = &ib[n * IWSTR + q * 4];
                const void* src = &g_in16[(size_t)(base + n) * 128 + kc * 16 + q * 4];
                if (n < nrem) cpa16(dst, src);
                else          cpa16_zero(dst, g_in16);
            }
        };

        stage(0, 0);
        cpa_commit();
        for (int kc = 0; kc < 8; kc++) {
            int cur = kc & 1;
            if (kc < 7) { stage(kc + 1, cur ^ 1); cpa_commit(); cpa_wait<1>(); }
            else        { cpa_wait<0>(); }
            __syncthreads();

            const u32* wS = wSb + cur * 2048;
            const u32* inS = iSb + cur * 1280;
#pragma unroll
            for (int ks = 0; ks < 2; ks++) {
                u32 b0[8], b1[8];
                int wb0 = ks * 1024 + wn * 512 + qr * 4 + qk;
#pragma unroll
                for (int nb = 0; nb < 8; nb++) {
                    b0[nb] = wS[wb0 + nb * 64];
                    b1[nb] = wS[wb0 + nb * 64 + 32];
                }
                u32 a[2][4];
#pragma unroll
                for (int mb = 0; mb < 2; mb++) {
                    int r0 = (wm * 32 + mb * 16 + qr) * IWSTR + ks * 8 + qk;
                    int r1 = r0 + 8 * IWSTR;
                    a[mb][0] = inS[r0];
                    a[mb][1] = inS[r1];
                    a[mb][2] = inS[r0 + 4];
                    a[mb][3] = inS[r1 + 4];
                }
#pragma unroll
                for (int mb = 0; mb < 2; mb++)
#pragma unroll
                    for (int nb = 0; nb < 8; nb++)
                        mma_f16(acc[mb][nb], a[mb][0], a[mb][1], a[mb][2], a[mb][3],
                                b0[nb], b1[nb]);
            }
            __syncthreads();
        }

        // Epilogue: bias, row L2 norm, store h (fp16), BN partials (fp32)
        float ssp[2][2] = {{0.f, 0.f}, {0.f, 0.f}};
#pragma unroll
        for (int mb = 0; mb < 2; mb++)
#pragma unroll
            for (int nb = 0; nb < 8; nb++) {
                acc[mb][nb][0] += bp[nb].x; acc[mb][nb][1] += bp[nb].y;
                acc[mb][nb][2] += bp[nb].x; acc[mb][nb][3] += bp[nb].y;
                ssp[mb][0] += acc[mb][nb][0] * acc[mb][nb][0] + acc[mb][nb][1] * acc[mb][nb][1];
                ssp[mb][1] += acc[mb][nb][2] * acc[mb][nb][2] + acc[mb][nb][3] * acc[mb][nb][3];
            }
#pragma unroll
        for (int mb = 0; mb < 2; mb++)
#pragma unroll
            for (int rs = 0; rs < 2; rs++) {
                ssp[mb][rs] += __shfl_xor_sync(0xffffffffu, ssp[mb][rs], 1);
                ssp[mb][rs] += __shfl_xor_sync(0xffffffffu, ssp[mb][rs], 2);
            }
        if (qk == 0) {
#pragma unroll
            for (int mb = 0; mb < 2; mb++)
#pragma unroll
                for (int rs = 0; rs < 2; rs++)
                    ssS[wn][wm * 32 + mb * 16 + rs * 8 + qr] = ssp[mb][rs];
        }
        __syncthreads();
        float inv[2][2];
#pragma unroll
        for (int mb = 0; mb < 2; mb++)
#pragma unroll
            for (int rs = 0; rs < 2; rs++) {
                int lr = wm * 32 + mb * 16 + rs * 8 + qr;
                float tot = ssS[0][lr] + ssS[1][lr];
                inv[mb][rs] = 1.f / fmaxf(sqrtf(tot), 1e-12f);
            }
#pragma unroll
        for (int mb = 0; mb < 2; mb++) {
            int lr0 = wm * 32 + mb * 16 + qr;
            int lr1 = lr0 + 8;
#pragma unroll
            for (int nb = 0; nb < 8; nb++) {
                int word = wn * 32 + nb * 4 + qk;
                if (lr0 < nrem) {
                    float vx = acc[mb][nb][0] * inv[mb][0];
                    float vy = acc[mb][nb][1] * inv[mb][0];
                    __half2 hv = __floats2half2_rn(vx, vy);
                    g_h16[(size_t)(base + lr0) * 64 + word] = *reinterpret_cast<u32*>(&hv);
                    s1[nb].x += vx; s1[nb].y += vy;
                    s2[nb].x += vx * vx; s2[nb].y += vy * vy;
                }
                if (lr1 < nrem) {
                    float vx = acc[mb][nb][2] * inv[mb][1];
                    float vy = acc[mb][nb][3] * inv[mb][1];
                    __half2 hv = __floats2half2_rn(vx, vy);
                    g_h16[(size_t)(base + lr1) * 64 + word] = *reinterpret_cast<u32*>(&hv);
                    s1[nb].x += vx; s1[nb].y += vy;
                    s2[nb].x += vx * vx; s2[nb].y += vy * vy;
                }
            }
        }
        __syncthreads();
    }

    // BN reduction
#pragma unroll
    for (int off = 4; off < 32; off <<= 1) {
#pragma unroll
        for (int nb = 0; nb < 8; nb++) {
            s1[nb].x += __shfl_xor_sync(0xffffffffu, s1[nb].x, off);
            s1[nb].y += __shfl_xor_sync(0xffffffffu, s1[nb].y, off);
            s2[nb].x += __shfl_xor_sync(0xffffffffu, s2[nb].x, off);
            s2[nb].y += __shfl_xor_sync(0xffffffffu, s2[nb].y, off);
        }
    }
    if (lane < 4) {
#pragma unroll
        for (int nb = 0; nb < 8; nb++) {
            int c = wn * 64 + nb * 8 + 2 * lane;
            bnstage[0][warp][c] = s1[nb].x; bnstage[0][warp][c + 1] = s1[nb].y;
            bnstage[1][warp][c] = s2[nb].x; bnstage[1][warp][c + 1] = s2[nb].y;
        }
    }
    __syncthreads();
    if (tid < 128) {
        int wsel = tid >> 6;
        float a0 = bnstage[0][wsel][tid] + bnstage[0][2 + wsel][tid];
        float a1 = bnstage[1][wsel][tid] + bnstage[1][2 + wsel][tid];
        atomicAdd(&g_bnsum[tid], a0);
        atomicAdd(&g_bnsq[tid], a1);
    }
}

__global__ void bn_finalize(const float* __restrict__ gamma, const float* __restrict__ beta, float invN) {
    int c = threadIdx.x;
    float mean = g_bnsum[c] * invN;
    float var = g_bnsq[c] * invN - mean * mean;
    float sc = gamma[c] * rsqrtf(var + 1e-5f);
    g_bnscale[c] = sc;
    g_bnshift[c] = beta[c] - mean * sc;
}

// ---------------------------------------------------------------------------
// GEMM2 (fp16 mma, 2-stage): out = L2norm_row(g_in @ W2 + b2l), 47 cols (48 pad)
// ---------------------------------------------------------------------------
__global__ void __launch_bounds__(128) sage_gemm2(
    const float* __restrict__ b2l, float* __restrict__ outp, int Nn)
{
    extern __shared__ u32 dyn[];
    u32* wSb = dyn;            // 2 * 768
    u32* iSb = dyn + 1536;     // 2 * 1280
    __shared__ float ssS[2][64];

    const int tid  = threadIdx.x;
    const int warp = tid >> 5, lane = tid & 31;
    const int wm = warp >> 1, wn = warp & 1;
    const int qr = lane >> 2, qk = lane & 3;

    float2 bp[3];
#pragma unroll
    for (int nb = 0; nb < 3; nb++) {
        int c = wn * 24 + nb * 8 + 2 * qk;
        bp[nb].x = (c < 47) ? b2l[c] : 0.f;
        bp[nb].y = (c + 1 < 47) ? b2l[c + 1] : 0.f;
    }

    for (int base = blockIdx.x * 64; base < Nn; base += gridDim.x * 64) {
        int nrem = min(64, Nn - base);

        float acc[2][3][4];
#pragma unroll
        for (int mb = 0; mb < 2; mb++)
#pragma unroll
            for (int nb = 0; nb < 3; nb++)
#pragma unroll
                for (int q = 0; q < 4; q++) acc[mb][nb][q] = 0.f;

        auto stage = [&](int kc, int buf) {
            u32* wdst = wSb + buf * 768;
            const u32* wsrc = g_wT2h + kc * 768;
            for (int i4 = tid; i4 < 192; i4 += 128) cpa16(&wdst[i4 * 4], &wsrc[i4 * 4]);
            u32* ib = iSb + buf * 1280;
            for (int i = tid; i < 256; i += 128) {
                int n = i >> 2, q = i & 3;
                void* dst = &ib[n * IWSTR + q * 4];
                const void* src = &g_in16[(size_t)(base + n) * 128 + kc * 16 + q * 4];
                if (n < nrem) cpa16(dst, src);
                else          cpa16_zero(dst, g_in16);
            }
        };

        stage(0, 0);
        cpa_commit();
        for (int kc = 0; kc < 8; kc++) {
            int cur = kc & 1;
            if (kc < 7) { stage(kc + 1, cur ^ 1); cpa_commit(); cpa_wait<1>(); }
            else        { cpa_wait<0>(); }
            __syncthreads();

            const u32* wS = wSb + cur * 768;
            const u32* inS = iSb + cur * 1280;
#pragma unroll
            for (int ks = 0; ks < 2; ks++) {
                u32 b0[3], b1[3];
                int wb0 = ks * 384 + wn * 192 + qr * 4 + qk;
#pragma unroll
                for (int nb = 0; nb < 3; nb++) {
                    b0[nb] = wS[wb0 + nb * 64];
                    b1[nb] = wS[wb0 + nb * 64 + 32];
                }
                u32 a[2][4];
#pragma unroll
                for (int mb = 0; mb < 2; mb++) {
                    int r0 = (wm * 32 + mb * 16 + qr) * IWSTR + ks * 8 + qk;
                    int r1 = r0 + 8 * IWSTR;
                    a[mb][0] = inS[r0];
                    a[mb][1] = inS[r1];
                    a[mb][2] = inS[r0 + 4];
                    a[mb][3] = inS[r1 + 4];
                }
#pragma unroll
                for (int mb = 0; mb < 2; mb++)
#pragma unroll
                    for (int nb = 0; nb < 3; nb++)
                        mma_f16(acc[mb][nb], a[mb][0], a[mb][1], a[mb][2], a[mb][3],
                                b0[nb], b1[nb]);
            }
            __syncthreads();
        }

        float ssp[2][2] = {{0.f, 0.f}, {0.f, 0.f}};
#pragma unroll
        for (int mb = 0; mb < 2; mb++)
#pragma unroll
            for (int nb = 0; nb < 3; nb++) {
                acc[mb][nb][0] += bp[nb].x; acc[mb][nb][1] += bp[nb].y;
                acc[mb][nb][2] += bp[nb].x; acc[mb][nb][3] += bp[nb].y;
                ssp[mb][0] += acc[mb][nb][0] * acc[mb][nb][0] + acc[mb][nb][1] * acc[mb][nb][1];
                ssp[mb][1] += acc[mb][nb][2] * acc[mb][nb][2] + acc[mb][nb][3] * acc[mb][nb][3];
            }
#pragma unroll
        for (int mb = 0; mb < 2; mb++)
#pragma unroll
            for (int rs = 0; rs < 2; rs++) {
                ssp[mb][rs] += __shfl_xor_sync(0xffffffffu, ssp[mb][rs], 1);
                ssp[mb][rs] += __shfl_xor_sync(0xffffffffu, ssp[mb][rs], 2);
            }
        if (qk == 0) {
#pragma unroll
            for (int mb = 0; mb < 2; mb++)
#pragma unroll
                for (int rs = 0; rs < 2; rs++)
                    ssS[wn][wm * 32 + mb * 16 + rs * 8 + qr] = ssp[mb][rs];
        }
        __syncthreads();
        float inv[2][2];
#pragma unroll
        for (int mb = 0; mb < 2; mb++)
#pragma unroll
            for (int rs = 0; rs < 2; rs++) {
                int lr = wm * 32 + mb * 16 + rs * 8 + qr;
                float tot = ssS[0][lr] + ssS[1][lr];
                inv[mb][rs] = 1.f / fmaxf(sqrtf(tot), 1e-12f);
            }
#pragma unroll
        for (int mb = 0; mb < 2; mb++) {
            int lr0 = wm * 32 + mb * 16 + qr;
            int lr1 = lr0 + 8;
#pragma unroll
            for (int nb = 0; nb < 3; nb++) {
                int c0 = wn * 24 + nb * 8 + 2 * qk;
                if (lr0 < nrem) {
                    size_t o = (size_t)(base + lr0) * 47;
                    if (c0 < 47)     outp[o + c0]     = acc[mb][nb][0] * inv[mb][0];
                    if (c0 + 1 < 47) outp[o + c0 + 1] = acc[mb][nb][1] * inv[mb][0];
                }
                if (lr1 < nrem) {
                    size_t o = (size_t)(base + lr1) * 47;
                    if (c0 < 47)     outp[o + c0]     = acc[mb][nb][2] * inv[mb][1];
                    if (c0 + 1 < 47) outp[o + c0 + 1] = acc[mb][nb][3] * inv[mb][1];
                }
            }
        }
        __syncthreads();
    }
}

// ---------------------------------------------------------------------------
extern "C" void kernel_launch(void* const* d_in, const int* in_sizes, int n_in,
                              void* d_out, int out_size) {
    const float* x     = (const float*)d_in[0];
    const void*  ei    = d_in[1];
    const float* w1l   = (const float*)d_in[2];
    const float* b1l   = (const float*)d_in[3];
    const float* w1r   = (const float*)d_in[4];
    const float* gamma = (const float*)d_in[5];
    const float* beta  = (const float*)d_in[6];
    const float* w2l   = (const float*)d_in[7];
    const float* b2l   = (const float*)d_in[8];
    const float* w2r   = (const float*)d_in[9];
    int Nn = in_sizes[0] / 128;
    int E  = in_sizes[1] / 2;

    int gb = (Nn + 63) / 64;
    int smem1 = (2 * 2048 + 2 * 1280) * 4;   // 26624 B
    int smem2 = (2 * 768 + 2 * 1280) * 4;    // 16384 B

    prep_all<<<1024, 256>>>(x, ei, w1l, w1r, w2l, w2r, Nn);
    build_adj<<<(E + 255) / 256, 256>>>(ei, E, Nn);
    gather_mean<<<2048, 256>>>(0, Nn);
    sage_gemm1<<<gb, 128, smem1>>>(b1l, Nn);
    bn_finalize<<<1, 128>>>(gamma, beta, 1.0f / (float)Nn);
    gather_mean<<<2048, 256>>>(1, Nn);
    sage_gemm2<<<gb, 128, smem2>>>(b2l, (float*)d_out, Nn);
}

// round 16
// speedup vs baseline: 1.1240x; 1.0147x over previous
#include <cuda_runtime.h>
#include <cuda_fp16.h>
#include <cstdint>
#include <cstddef>

// ---------------------------------------------------------------------------
// GraphSAGE 2-layer (N=100000, E=800000, 128 -> 128 -> 47, fp32 in/out):
//   prep(dtype+weights+zero+x->fp16) -> adjacency build ->
//   gather([agg|self] fp16) -> GEMM1(fp16 mma, vectorized B-fragment LDS.128,
//   2-stage cp.async, +bias+L2norm+BN) -> BN finalize -> gather(+BN+ReLU) ->
//   GEMM2(fp16 mma) -> out
// W1 layout: per (kc,ks,wn) slab, per lane 16 contiguous words = 4 uint4
// B-fragment packs with (j+lane/2)&3 rotation (conflict-free LDS.128).
// GEMM blocks stay 128 threads (co-resident CTAs = latency hiding).
// Device-global pointers always selected INSIDE kernels (GB300 ATS trap).
// ---------------------------------------------------------------------------

#define NMAX 100000
#define IWSTR 20         // inS row stride in u32 words (40 halves)
#define SLOTS 64

typedef unsigned long long u64;
typedef unsigned int u32;

__device__ __align__(16) u32  g_x16[(size_t)NMAX * 64];    // x as fp16
__device__ __align__(16) u32  g_h16[(size_t)NMAX * 64];    // h as fp16
__device__ __align__(16) u32  g_in16[(size_t)NMAX * 128];  // [agg|self] fp16
__device__ __align__(16) int  g_cnt[NMAX];
__device__ __align__(16) int  g_slot[(size_t)NMAX * SLOTS];
__device__ __align__(16) u32  g_wT1h[16384];  // fp16, vectorized frag packs
__device__ __align__(16) u32  g_wT2h[6144];   // fp16, scalar frag order
__device__ __align__(16) float g_bnsum[128];
__device__ __align__(16) float g_bnsq[128];
__device__ __align__(16) float g_bnscale[128];
__device__ __align__(16) float g_bnshift[128];
__device__ int g_ei32;

// ---- helpers ---------------------------------------------------------------
__device__ __forceinline__ void mma_f16(float* c, u32 a0, u32 a1, u32 a2, u32 a3,
                                        u32 b0, u32 b1) {
    asm volatile(
        "mma.sync.aligned.m16n8k16.row.col.f32.f16.f16.f32 "
        "{%0,%1,%2,%3}, {%4,%5,%6,%7}, {%8,%9}, {%0,%1,%2,%3};"
        : "+f"(c[0]), "+f"(c[1]), "+f"(c[2]), "+f"(c[3])
        : "r"(a0), "r"(a1), "r"(a2), "r"(a3), "r"(b0), "r"(b1));
}
__device__ __forceinline__ void cpa16(void* smem, const void* g) {
    u32 s = (u32)__cvta_generic_to_shared(smem);
    asm volatile("cp.async.cg.shared.global [%0], [%1], 16;" :: "r"(s), "l"(g));
}
__device__ __forceinline__ void cpa16_zero(void* smem, const void* g) {
    u32 s = (u32)__cvta_generic_to_shared(smem);
    asm volatile("cp.async.cg.shared.global [%0], [%1], 16, %2;"
                 :: "r"(s), "l"(g), "r"(0u));
}
__device__ __forceinline__ void cpa_commit() {
    asm volatile("cp.async.commit_group;" ::: "memory");
}
template<int N> __device__ __forceinline__ void cpa_wait() {
    asm volatile("cp.async.wait_group %0;" :: "n"(N) : "memory");
}
__device__ __forceinline__ float4 bnrelu4(float4 v, float4 sc, float4 sh) {
    v.x = fmaxf(fmaf(v.x, sc.x, sh.x), 0.f);
    v.y = fmaxf(fmaf(v.y, sc.y, sh.y), 0.f);
    v.z = fmaxf(fmaf(v.z, sc.z, sh.z), 0.f);
    v.w = fmaxf(fmaf(v.w, sc.w, sh.w), 0.f);
    return v;
}
__device__ __forceinline__ float4 unpack_h4(uint2 u) {
    float2 f0 = __half22float2(*reinterpret_cast<__half2*>(&u.x));
    float2 f1 = __half22float2(*reinterpret_cast<__half2*>(&u.y));
    return make_float4(f0.x, f0.y, f1.x, f1.y);
}
__device__ __forceinline__ uint2 pack_h4(float4 v) {
    __half2 p0 = __floats2half2_rn(v.x, v.y);
    __half2 p1 = __floats2half2_rn(v.z, v.w);
    uint2 o;
    o.x = *reinterpret_cast<u32*>(&p0);
    o.y = *reinterpret_cast<u32*>(&p1);
    return o;
}

// ---------------------------------------------------------------------------
// prep: dtype detect, fp16 weights, zero cnt/BN, x -> fp16.
// W1 word dest = w, decoded as: kk=w>>10 (k16 slab), wn=(w>>9)&1,
// lane=(w>>4)&31, widx=w&15; widx = rot*4 + (nb&1)*2 + hs with
// rot = ((nb>>1) + (lane>>1)) & 3;  qr=lane>>2, tt=lane&3;
// value = half2(W[wn*64+nb*8+qr][kk*16+hs*8+2*tt], ...+1).
__global__ void __launch_bounds__(256) prep_all(
    const float* __restrict__ x, const void* __restrict__ ei,
    const float* __restrict__ w1l, const float* __restrict__ w1r,
    const float* __restrict__ w2l, const float* __restrict__ w2r, int Nn)
{
    int t = blockIdx.x * blockDim.x + threadIdx.x;
    int stride = gridDim.x * blockDim.x;
    if (blockIdx.x == 0 && threadIdx.x < 32) {
        int lane = threadIdx.x;
        long long v = ((const long long*)ei)[lane & 15];
        unsigned bad = __ballot_sync(0xffffffffu, v < 0 || v >= (long long)Nn);
        if (lane == 0) g_ei32 = bad ? 1 : 0;
    }
    for (int w = t; w < 16384; w += stride) {
        int kk   = w >> 10;
        int r    = w & 1023;
        int wn   = r >> 9;
        int lane = (r >> 4) & 31;
        int widx = w & 15;
        int rot  = widx >> 2;
        int nbhi = (rot - (lane >> 1)) & 3;
        int nb   = (nbhi << 1) | ((widx >> 1) & 1);
        int hs   = widx & 1;
        int qr   = lane >> 2;
        int tt   = lane & 3;
        int col  = wn * 64 + nb * 8 + qr;
        int k0   = kk * 16 + hs * 8 + 2 * tt;
        float v0 = (k0 < 128) ? w1l[col * 128 + k0] : w1r[col * 128 + k0 - 128];
        int k1 = k0 + 1;
        float v1 = (k1 < 128) ? w1l[col * 128 + k1] : w1r[col * 128 + k1 - 128];
        __half2 h = __floats2half2_rn(v0, v1);
        g_wT1h[w] = *reinterpret_cast<u32*>(&h);
    }
    for (int w = t; w < 6144; w += stride) {
        int kk = w / 384;
        int r = w - kk * 384;
        int nb = r >> 6;
        int r2 = r & 63;
        int hs = r2 >> 5;
        int r3 = r2 & 31;
        int cib = r3 >> 2;
        int tt = r3 & 3;
        int col = nb * 8 + cib;
        int k0 = kk * 16 + 2 * tt + hs * 8;
        float v0 = 0.f, v1 = 0.f;
        if (col < 47) {
            v0 = (k0 < 128) ? w2l[col * 128 + k0] : w2r[col * 128 + k0 - 128];
            v1 = (k0 + 1 < 128) ? w2l[col * 128 + k0 + 1] : w2r[col * 128 + k0 + 1 - 128];
        }
        __half2 h = __floats2half2_rn(v0, v1);
        int dest = (kk >> 1) * 768 + (kk & 1) * 384 + nb * 64 + hs * 32 + cib * 4 + tt;
        g_wT2h[dest] = *reinterpret_cast<u32*>(&h);
    }
    for (int j = t; j < Nn; j += stride) g_cnt[j] = 0;
    if (t < 128) { g_bnsum[t] = 0.f; g_bnsq[t] = 0.f; }
    const float4* x4 = (const float4*)x;
    uint2* out = (uint2*)g_x16;
    int n4 = Nn * 32;
    for (int j = t; j < n4; j += stride) out[j] = pack_h4(x4[j]);
}

__global__ void __launch_bounds__(256) build_adj(
    const void* __restrict__ ei, int E, int Nn)
{
    const int is32 = g_ei32;
    int t = blockIdx.x * blockDim.x + threadIdx.x;
    int stride = gridDim.x * blockDim.x;
    for (int e = t; e < E; e += stride) {
        int src, dst;
        if (is32) {
            src = ((const int*)ei)[e];
            dst = ((const int*)ei)[(size_t)E + e];
        } else {
            src = (int)((const long long*)ei)[e];
            dst = (int)((const long long*)ei)[(size_t)E + e];
        }
        if ((unsigned)src >= (unsigned)Nn || (unsigned)dst >= (unsigned)Nn) continue;
        int pos = atomicAdd(&g_cnt[dst], 1);
        if (pos < SLOTS) g_slot[(size_t)dst * SLOTS + pos] = src;
    }
}

// Gather: one warp per node; lane owns channels 4l..4l+3.
// srcSel: 0 -> g_x16 (layer 1), 1 -> g_h16 with BN+ReLU (layer 2).
__global__ void __launch_bounds__(256, 6) gather_mean(int srcSel, int Nn)
{
    const uint2* feat2 = srcSel ? (const uint2*)g_h16 : (const uint2*)g_x16;
    const int withBN = srcSel;
    int gw   = (blockIdx.x * blockDim.x + threadIdx.x) >> 5;
    int lane = threadIdx.x & 31;
    int nw   = (gridDim.x * blockDim.x) >> 5;
    float4 sc = make_float4(1.f, 1.f, 1.f, 1.f);
    float4 sh = make_float4(0.f, 0.f, 0.f, 0.f);
    if (withBN) {
        sc = ((const float4*)g_bnscale)[lane];
        sh = ((const float4*)g_bnshift)[lane];
    }
    uint2* out2 = (uint2*)g_in16;
    for (int n = gw; n < Nn; n += nw) {
        int cnt = g_cnt[n];
        int m = min(cnt, SLOTS);
        const int* sl = g_slot + (size_t)n * SLOTS;
        float4 a = make_float4(0.f, 0.f, 0.f, 0.f);
        int j = 0;
        for (; j + 4 <= m; j += 4) {
            float4 v0 = unpack_h4(feat2[(size_t)sl[j]     * 32 + lane]);
            float4 v1 = unpack_h4(feat2[(size_t)sl[j + 1] * 32 + lane]);
            float4 v2 = unpack_h4(feat2[(size_t)sl[j + 2] * 32 + lane]);
            float4 v3 = unpack_h4(feat2[(size_t)sl[j + 3] * 32 + lane]);
            if (withBN) {
                v0 = bnrelu4(v0, sc, sh); v1 = bnrelu4(v1, sc, sh);
                v2 = bnrelu4(v2, sc, sh); v3 = bnrelu4(v3, sc, sh);
            }
            a.x += (v0.x + v1.x) + (v2.x + v3.x);
            a.y += (v0.y + v1.y) + (v2.y + v3.y);
            a.z += (v0.z + v1.z) + (v2.z + v3.z);
            a.w += (v0.w + v1.w) + (v2.w + v3.w);
        }
        for (; j < m; j++) {
            float4 v = unpack_h4(feat2[(size_t)sl[j] * 32 + lane]);
            if (withBN) v = bnrelu4(v, sc, sh);
            a.x += v.x; a.y += v.y; a.z += v.z; a.w += v.w;
        }
        float r = 1.f / fmaxf((float)cnt, 1.f);
        a.x *= r; a.y *= r; a.z *= r; a.w *= r;
        out2[(size_t)n * 64 + lane] = pack_h4(a);
        float4 s = unpack_h4(feat2[(size_t)n * 32 + lane]);
        if (withBN) s = bnrelu4(s, sc, sh);
        out2[(size_t)n * 64 + 32 + lane] = pack_h4(s);
    }
}

// ---------------------------------------------------------------------------
// GEMM1 (fp16 mma m16n8k16, 2-stage cp.async): h = L2norm_row(g_in @ W1 + b1l)
// 128 threads = 4 warps (wm,wn 2x2); 64-node x 128-ch tile.
// B-fragments via 4x LDS.128 per ks-slab (rotated pack layout).
// ---------------------------------------------------------------------------
__global__ void __launch_bounds__(128) sage_gemm1(
    const float* __restrict__ bias, int Nn)
{
    extern __shared__ u32 dyn[];
    u32* wSb = dyn;            // 2 * 2048
    u32* iSb = dyn + 4096;     // 2 * 1280
    __shared__ float ssS[2][64];
    __shared__ float bnstage[2][4][128];

    const int tid  = threadIdx.x;
    const int warp = tid >> 5, lane = tid & 31;
    const int wm = warp >> 1, wn = warp & 1;
    const int qr = lane >> 2, qk = lane & 3;

    float2 bp[8];
#pragma unroll
    for (int nb = 0; nb < 8; nb++)
        bp[nb] = *(const float2*)&bias[wn * 64 + nb * 8 + 2 * qk];

    for (int base = blockIdx.x * 64; base < Nn; base += gridDim.x * 64) {
        int nrem = min(64, Nn - base);

        float acc[2][8][4];
#pragma unroll
        for (int mb = 0; mb < 2; mb++)
#pragma unroll
            for (int nb = 0; nb < 8; nb++)
#pragma unroll
                for (int q = 0; q < 4; q++) acc[mb][nb][q] = 0.f;

        auto stage = [&](int kc, int buf) {
            u32* wdst = wSb + buf * 2048;
            const u32* wsrc = g_wT1h + kc * 2048;
            for (int i4 = tid; i4 < 512; i4 += 128) cpa16(&wdst[i4 * 4], &wsrc[i4 * 4]);
            u32* ib = iSb + buf * 1280;
            for (int i = tid; i < 256; i += 128) {
                int n = i >> 2, q = i & 3;
                void* dst = &ib[n * IWSTR + q * 4];
                const void* src = &g_in16[(size_t)(base + n) * 128 + kc * 16 + q * 4];
                if (n < nrem) cpa16(dst, src);
                else          cpa16_zero(dst, g_in16);
            }
        };

        stage(0, 0);
        cpa_commit();
        for (int kc = 0; kc < 8; kc++) {
            int cur = kc & 1;
            if (kc < 7) { stage(kc + 1, cur ^ 1); cpa_commit(); cpa_wait<1>(); }
            else        { cpa_wait<0>(); }
            __syncthreads();

            const u32* wS = wSb + cur * 2048;
            const u32* inS = iSb + cur * 1280;
#pragma unroll
            for (int ks = 0; ks < 2; ks++) {
                u32 b0[8], b1[8];
                const uint4* wv = (const uint4*)(wS + ks * 1024 + wn * 512 + lane * 16);
#pragma unroll
                for (int j = 0; j < 4; j++) {
                    uint4 wq = wv[(j + (lane >> 1)) & 3];
                    b0[2 * j]     = wq.x; b1[2 * j]     = wq.y;
                    b0[2 * j + 1] = wq.z; b1[2 * j + 1] = wq.w;
                }
                u32 a[2][4];
#pragma unroll
                for (int mb = 0; mb < 2; mb++) {
                    int r0 = (wm * 32 + mb * 16 + qr) * IWSTR + ks * 8 + qk;
                    int r1 = r0 + 8 * IWSTR;
                    a[mb][0] = inS[r0];
                    a[mb][1] = inS[r1];
                    a[mb][2] = inS[r0 + 4];
                    a[mb][3] = inS[r1 + 4];
                }
#pragma unroll
                for (int mb = 0; mb < 2; mb++)
#pragma unroll
                    for (int nb = 0; nb < 8; nb++)
                        mma_f16(acc[mb][nb], a[mb][0], a[mb][1], a[mb][2], a[mb][3],
                                b0[nb], b1[nb]);
            }
            __syncthreads();
        }

        // Epilogue: bias, row L2 norm, store h (fp16), BN partials (fp32).
        float2 s1[8], s2[8];
#pragma unroll
        for (int nb = 0; nb < 8; nb++) { s1[nb] = make_float2(0.f, 0.f); s2[nb] = make_float2(0.f, 0.f); }

        float ssp[2][2] = {{0.f, 0.f}, {0.f, 0.f}};
#pragma unroll
        for (int mb = 0; mb < 2; mb++)
#pragma unroll
            for (int nb = 0; nb < 8; nb++) {
                acc[mb][nb][0] += bp[nb].x; acc[mb][nb][1] += bp[nb].y;
                acc[mb][nb][2] += bp[nb].x; acc[mb][nb][3] += bp[nb].y;
                ssp[mb][0] += acc[mb][nb][0] * acc[mb][nb][0] + acc[mb][nb][1] * acc[mb][nb][1];
                ssp[mb][1] += acc[mb][nb][2] * acc[mb][nb][2] + acc[mb][nb][3] * acc[mb][nb][3];
            }
#pragma unroll
        for (int mb = 0; mb < 2; mb++)
#pragma unroll
            for (int rs = 0; rs < 2; rs++) {
                ssp[mb][rs] += __shfl_xor_sync(0xffffffffu, ssp[mb][rs], 1);
                ssp[mb][rs] += __shfl_xor_sync(0xffffffffu, ssp[mb][rs], 2);
            }
        if (qk == 0) {
#pragma unroll
            for (int mb = 0; mb < 2; mb++)
#pragma unroll
                for (int rs = 0; rs < 2; rs++)
                    ssS[wn][wm * 32 + mb * 16 + rs * 8 + qr] = ssp[mb][rs];
        }
        __syncthreads();
        float inv[2][2];
#pragma unroll
        for (int mb = 0; mb < 2; mb++)
#pragma unroll
            for (int rs = 0; rs < 2; rs++) {
                int lr = wm * 32 + mb * 16 + rs * 8 + qr;
                float tot = ssS[0][lr] + ssS[1][lr];
                inv[mb][rs] = 1.f / fmaxf(sqrtf(tot), 1e-12f);
            }
#pragma unroll
        for (int mb = 0; mb < 2; mb++) {
            int lr0 = wm * 32 + mb * 16 + qr;
            int lr1 = lr0 + 8;
#pragma unroll
            for (int nb = 0; nb < 8; nb++) {
                int word = wn * 32 + nb * 4 + qk;
                if (lr0 < nrem) {
                    float vx = acc[mb][nb][0] * inv[mb][0];
                    float vy = acc[mb][nb][1] * inv[mb][0];
                    __half2 hv = __floats2half2_rn(vx, vy);
                    g_h16[(size_t)(base + lr0) * 64 + word] = *reinterpret_cast<u32*>(&hv);
                    s1[nb].x += vx; s1[nb].y += vy;
                    s2[nb].x += vx * vx; s2[nb].y += vy * vy;
                }
                if (lr1 < nrem) {
                    float vx = acc[mb][nb][2] * inv[mb][1];
                    float vy = acc[mb][nb][3] * inv[mb][1];
                    __half2 hv = __floats2half2_rn(vx, vy);
                    g_h16[(size_t)(base + lr1) * 64 + word] = *reinterpret_cast<u32*>(&hv);
                    s1[nb].x += vx; s1[nb].y += vy;
                    s2[nb].x += vx * vx; s2[nb].y += vy * vy;
                }
            }
        }

        // BN reduction for this tile: shuffle, stage, 1 atomic per channel.
#pragma unroll
        for (int off = 4; off < 32; off <<= 1) {
#pragma unroll
            for (int nb = 0; nb < 8; nb++) {
                s1[nb].x += __shfl_xor_sync(0xffffffffu, s1[nb].x, off);
                s1[nb].y += __shfl_xor_sync(0xffffffffu, s1[nb].y, off);
                s2[nb].x += __shfl_xor_sync(0xffffffffu, s2[nb].x, off);
                s2[nb].y += __shfl_xor_sync(0xffffffffu, s2[nb].y, off);
            }
        }
        if (lane < 4) {
#pragma unroll
            for (int nb = 0; nb < 8; nb++) {
                int c = wn * 64 + nb * 8 + 2 * lane;
                bnstage[0][warp][c] = s1[nb].x; bnstage[0][warp][c + 1] = s1[nb].y;
                bnstage[1][warp][c] = s2[nb].x; bnstage[1][warp][c + 1] = s2[nb].y;
            }
        }
        __syncthreads();
        if (tid < 128) {
            int wsel = tid >> 6;
            float a0 = bnstage[0][wsel][tid] + bnstage[0][2 + wsel][tid];
            float a1 = bnstage[1][wsel][tid] + bnstage[1][2 + wsel][tid];
            atomicAdd(&g_bnsum[tid], a0);
            atomicAdd(&g_bnsq[tid], a1);
        }
        __syncthreads();
    }
}

__global__ void bn_finalize(const float* __restrict__ gamma, const float* __restrict__ beta, float invN) {
    int c = threadIdx.x;
    float mean = g_bnsum[c] * invN;
    float var = g_bnsq[c] * invN - mean * mean;
    float sc = gamma[c] * rsqrtf(var + 1e-5f);
    g_bnscale[c] = sc;
    g_bnshift[c] = beta[c] - mean * sc;
}

// ---------------------------------------------------------------------------
// GEMM2 (fp16 mma, 2-stage): out = L2norm_row(g_in @ W2 + b2l), 47 cols (48 pad)
// ---------------------------------------------------------------------------
__global__ void __launch_bounds__(128) sage_gemm2(
    const float* __restrict__ b2l, float* __restrict__ outp, int Nn)
{
    extern __shared__ u32 dyn[];
    u32* wSb = dyn;            // 2 * 768
    u32* iSb = dyn + 1536;     // 2 * 1280
    __shared__ float ssS[2][64];

    const int tid  = threadIdx.x;
    const int warp = tid >> 5, lane = tid & 31;
    const int wm = warp >> 1, wn = warp & 1;
    const int qr = lane >> 2, qk = lane & 3;

    float2 bp[3];
#pragma unroll
    for (int nb = 0; nb < 3; nb++) {
        int c = wn * 24 + nb * 8 + 2 * qk;
        bp[nb].x = (c < 47) ? b2l[c] : 0.f;
        bp[nb].y = (c + 1 < 47) ? b2l[c + 1] : 0.f;
    }

    for (int base = blockIdx.x * 64; base < Nn; base += gridDim.x * 64) {
        int nrem = min(64, Nn - base);

        float acc[2][3][4];
#pragma unroll
        for (int mb = 0; mb < 2; mb++)
#pragma unroll
            for (int nb = 0; nb < 3; nb++)
#pragma unroll
                for (int q = 0; q < 4; q++) acc[mb][nb][q] = 0.f;

        auto stage = [&](int kc, int buf) {
            u32* wdst = wSb + buf * 768;
            const u32* wsrc = g_wT2h + kc * 768;
            for (int i4 = tid; i4 < 192; i4 += 128) cpa16(&wdst[i4 * 4], &wsrc[i4 * 4]);
            u32* ib = iSb + buf * 1280;
            for (int i = tid; i < 256; i += 128) {
                int n = i >> 2, q = i & 3;
                void* dst = &ib[n * IWSTR + q * 4];
                const void* src = &g_in16[(size_t)(base + n) * 128 + kc * 16 + q * 4];
                if (n < nrem) cpa16(dst, src);
                else          cpa16_zero(dst, g_in16);
            }
        };

        stage(0, 0);
        cpa_commit();
        for (int kc = 0; kc < 8; kc++) {
            int cur = kc & 1;
            if (kc < 7) { stage(kc + 1, cur ^ 1); cpa_commit(); cpa_wait<1>(); }
            else        { cpa_wait<0>(); }
            __syncthreads();

            const u32* wS = wSb + cur * 768;
            const u32* inS = iSb + cur * 1280;
#pragma unroll
            for (int ks = 0; ks < 2; ks++) {
                u32 b0[3], b1[3];
                int wb0 = ks * 384 + wn * 192 + qr * 4 + qk;
#pragma unroll
                for (int nb = 0; nb < 3; nb++) {
                    b0[nb] = wS[wb0 + nb * 64];
                    b1[nb] = wS[wb0 + nb * 64 + 32];
                }
                u32 a[2][4];
#pragma unroll
                for (int mb = 0; mb < 2; mb++) {
                    int r0 = (wm * 32 + mb * 16 + qr) * IWSTR + ks * 8 + qk;
                    int r1 = r0 + 8 * IWSTR;
                    a[mb][0] = inS[r0];
                    a[mb][1] = inS[r1];
                    a[mb][2] = inS[r0 + 4];
                    a[mb][3] = inS[r1 + 4];
                }
#pragma unroll
                for (int mb = 0; mb < 2; mb++)
#pragma unroll
                    for (int nb = 0; nb < 3; nb++)
                        mma_f16(acc[mb][nb], a[mb][0], a[mb][1], a[mb][2], a[mb][3],
                                b0[nb], b1[nb]);
            }
            __syncthreads();
        }

        float ssp[2][2] = {{0.f, 0.f}, {0.f, 0.f}};
#pragma unroll
        for (int mb = 0; mb < 2; mb++)
#pragma unroll
            for (int nb = 0; nb < 3; nb++) {
                acc[mb][nb][0] += bp[nb].x; acc[mb][nb][1] += bp[nb].y;
                acc[mb][nb][2] += bp[nb].x; acc[mb][nb][3] += bp[nb].y;
                ssp[mb][0] += acc[mb][nb][0] * acc[mb][nb][0] + acc[mb][nb][1] * acc[mb][nb][1];
                ssp[mb][1] += acc[mb][nb][2] * acc[mb][nb][2] + acc[mb][nb][3] * acc[mb][nb][3];
            }
#pragma unroll
        for (int mb = 0; mb < 2; mb++)
#pragma unroll
            for (int rs = 0; rs < 2; rs++) {
                ssp[mb][rs] += __shfl_xor_sync(0xffffffffu, ssp[mb][rs], 1);
                ssp[mb][rs] += __shfl_xor_sync(0xffffffffu, ssp[mb][rs], 2);
            }
        if (qk == 0) {
#pragma unroll
            for (int mb = 0; mb < 2; mb++)
#pragma unroll
                for (int rs = 0; rs < 2; rs++)
                    ssS[wn][wm * 32 + mb * 16 + rs * 8 + qr] = ssp[mb][rs];
        }
        __syncthreads();
        float inv[2][2];
#pragma unroll
        for (int mb = 0; mb < 2; mb++)
#pragma unroll
            for (int rs = 0; rs < 2; rs++) {
                int lr = wm * 32 + mb * 16 + rs * 8 + qr;
                float tot = ssS[0][lr] + ssS[1][lr];
                inv[mb][rs] = 1.f / fmaxf(sqrtf(tot), 1e-12f);
            }
#pragma unroll
        for (int mb = 0; mb < 2; mb++) {
            int lr0 = wm * 32 + mb * 16 + qr;
            int lr1 = lr0 + 8;
#pragma unroll
            for (int nb = 0; nb < 3; nb++) {
                int c0 = wn * 24 + nb * 8 + 2 * qk;
                if (lr0 < nrem) {
                    size_t o = (size_t)(base + lr0) * 47;
                    if (c0 < 47)     outp[o + c0]     = acc[mb][nb][0] * inv[mb][0];
                    if (c0 + 1 < 47) outp[o + c0 + 1] = acc[mb][nb][1] * inv[mb][0];
                }
                if (lr1 < nrem) {
                    size_t o = (size_t)(base + lr1) * 47;
                    if (c0 < 47)     outp[o + c0]     = acc[mb][nb][2] * inv[mb][1];
                    if (c0 + 1 < 47) outp[o + c0 + 1] = acc[mb][nb][3] * inv[mb][1];
                }
            }
        }
        __syncthreads();
    }
}

// ---------------------------------------------------------------------------
extern "C" void kernel_launch(void* const* d_in, const int* in_sizes, int n_in,
                              void* d_out, int out_size) {
    const float* x     = (const float*)d_in[0];
    const void*  ei    = d_in[1];
    const float* w1l   = (const float*)d_in[2];
    const float* b1l   = (const float*)d_in[3];
    const float* w1r   = (const float*)d_in[4];
    const float* gamma = (const float*)d_in[5];
    const float* beta  = (const float*)d_in[6];
    const float* w2l   = (const float*)d_in[7];
    const float* b2l   = (const float*)d_in[8];
    const float* w2r   = (const float*)d_in[9];
    int Nn = in_sizes[0] / 128;
    int E  = in_sizes[1] / 2;

    int gb = (Nn + 63) / 64;
    int smem1 = (2 * 2048 + 2 * 1280) * 4;   // 26624 B
    int smem2 = (2 * 768 + 2 * 1280) * 4;    // 16384 B

    prep_all<<<1024, 256>>>(x, ei, w1l, w1r, w2l, w2r, Nn);
    build_adj<<<(E + 255) / 256, 256>>>(ei, E, Nn);
    gather_mean<<<2048, 256>>>(0, Nn);
    sage_gemm1<<<gb, 128, smem1>>>(b1l, Nn);
    bn_finalize<<<1, 128>>>(gamma, beta, 1.0f / (float)Nn);
    gather_mean<<<2048, 256>>>(1, Nn);
    sage_gemm2<<<gb, 128, smem2>>>(b2l, (float*)d_out, Nn);
}

// round 17
// speedup vs baseline: 1.1590x; 1.0312x over previous
#include <cuda_runtime.h>
#include <cuda_fp16.h>
#include <cstdint>
#include <cstddef>

// ---------------------------------------------------------------------------
// GraphSAGE 2-layer (N=100000, E=800000, 128 -> 128 -> 47, fp32 in/out):
//   prep(dtype+weights+zero+x->fp16) -> adjacency build ->
//   gather(agg-only fp16) -> GEMM1(fp16 mma, 3-stage cp.async, self half
//   staged straight from g_x16, +bias+L2norm+BN) -> BN finalize ->
//   gather(agg+bnrelu-self) -> GEMM2(fp16 mma, 2-stage) -> out
// GEMM blocks stay 128 threads (co-resident CTAs = latency hiding).
// Device-global pointers always selected INSIDE kernels (GB300 ATS trap).
// ---------------------------------------------------------------------------

#define NMAX 100000
#define IWSTR 20         // inS row stride in u32 words (40 halves)
#define SLOTS 64

typedef unsigned long long u64;
typedef unsigned int u32;

__device__ __align__(16) u32  g_x16[(size_t)NMAX * 64];    // x as fp16
__device__ __align__(16) u32  g_h16[(size_t)NMAX * 64];    // h as fp16
__device__ __align__(16) u32  g_in16[(size_t)NMAX * 128];  // L1: agg (64w rows); L2: [agg|self] (128w rows)
__device__ __align__(16) int  g_cnt[NMAX];
__device__ __align__(16) int  g_slot[(size_t)NMAX * SLOTS];
__device__ __align__(16) u32  g_wT1h[16384];  // fp16, vectorized frag packs
__device__ __align__(16) u32  g_wT2h[6144];   // fp16, scalar frag order
__device__ __align__(16) float g_bnsum[128];
__device__ __align__(16) float g_bnsq[128];
__device__ __align__(16) float g_bnscale[128];
__device__ __align__(16) float g_bnshift[128];
__device__ int g_ei32;

// ---- helpers ---------------------------------------------------------------
__device__ __forceinline__ void mma_f16(float* c, u32 a0, u32 a1, u32 a2, u32 a3,
                                        u32 b0, u32 b1) {
    asm volatile(
        "mma.sync.aligned.m16n8k16.row.col.f32.f16.f16.f32 "
        "{%0,%1,%2,%3}, {%4,%5,%6,%7}, {%8,%9}, {%0,%1,%2,%3};"
        : "+f"(c[0]), "+f"(c[1]), "+f"(c[2]), "+f"(c[3])
        : "r"(a0), "r"(a1), "r"(a2), "r"(a3), "r"(b0), "r"(b1));
}
__device__ __forceinline__ void cpa16(void* smem, const void* g) {
    u32 s = (u32)__cvta_generic_to_shared(smem);
    asm volatile("cp.async.cg.shared.global [%0], [%1], 16;" :: "r"(s), "l"(g));
}
__device__ __forceinline__ void cpa16_zero(void* smem, const void* g) {
    u32 s = (u32)__cvta_generic_to_shared(smem);
    asm volatile("cp.async.cg.shared.global [%0], [%1], 16, %2;"
                 :: "r"(s), "l"(g), "r"(0u));
}
__device__ __forceinline__ void cpa_commit() {
    asm volatile("cp.async.commit_group;" ::: "memory");
}
template<int N> __device__ __forceinline__ void cpa_wait() {
    asm volatile("cp.async.wait_group %0;" :: "n"(N) : "memory");
}
__device__ __forceinline__ float4 bnrelu4(float4 v, float4 sc, float4 sh) {
    v.x = fmaxf(fmaf(v.x, sc.x, sh.x), 0.f);
    v.y = fmaxf(fmaf(v.y, sc.y, sh.y), 0.f);
    v.z = fmaxf(fmaf(v.z, sc.z, sh.z), 0.f);
    v.w = fmaxf(fmaf(v.w, sc.w, sh.w), 0.f);
    return v;
}
__device__ __forceinline__ float4 unpack_h4(uint2 u) {
    float2 f0 = __half22float2(*reinterpret_cast<__half2*>(&u.x));
    float2 f1 = __half22float2(*reinterpret_cast<__half2*>(&u.y));
    return make_float4(f0.x, f0.y, f1.x, f1.y);
}
__device__ __forceinline__ uint2 pack_h4(float4 v) {
    __half2 p0 = __floats2half2_rn(v.x, v.y);
    __half2 p1 = __floats2half2_rn(v.z, v.w);
    uint2 o;
    o.x = *reinterpret_cast<u32*>(&p0);
    o.y = *reinterpret_cast<u32*>(&p1);
    return o;
}

// ---------------------------------------------------------------------------
// prep: dtype detect, fp16 weights, zero cnt/BN, x -> fp16.
__global__ void __launch_bounds__(256) prep_all(
    const float* __restrict__ x, const void* __restrict__ ei,
    const float* __restrict__ w1l, const float* __restrict__ w1r,
    const float* __restrict__ w2l, const float* __restrict__ w2r, int Nn)
{
    int t = blockIdx.x * blockDim.x + threadIdx.x;
    int stride = gridDim.x * blockDim.x;
    if (blockIdx.x == 0 && threadIdx.x < 32) {
        int lane = threadIdx.x;
        long long v = ((const long long*)ei)[lane & 15];
        unsigned bad = __ballot_sync(0xffffffffu, v < 0 || v >= (long long)Nn);
        if (lane == 0) g_ei32 = bad ? 1 : 0;
    }
    for (int w = t; w < 16384; w += stride) {
        int kk   = w >> 10;
        int r    = w & 1023;
        int wn   = r >> 9;
        int lane = (r >> 4) & 31;
        int widx = w & 15;
        int rot  = widx >> 2;
        int nbhi = (rot - (lane >> 1)) & 3;
        int nb   = (nbhi << 1) | ((widx >> 1) & 1);
        int hs   = widx & 1;
        int qr   = lane >> 2;
        int tt   = lane & 3;
        int col  = wn * 64 + nb * 8 + qr;
        int k0   = kk * 16 + hs * 8 + 2 * tt;
        float v0 = (k0 < 128) ? w1l[col * 128 + k0] : w1r[col * 128 + k0 - 128];
        int k1 = k0 + 1;
        float v1 = (k1 < 128) ? w1l[col * 128 + k1] : w1r[col * 128 + k1 - 128];
        __half2 h = __floats2half2_rn(v0, v1);
        g_wT1h[w] = *reinterpret_cast<u32*>(&h);
    }
    for (int w = t; w < 6144; w += stride) {
        int kk = w / 384;
        int r = w - kk * 384;
        int nb = r >> 6;
        int r2 = r & 63;
        int hs = r2 >> 5;
        int r3 = r2 & 31;
        int cib = r3 >> 2;
        int tt = r3 & 3;
        int col = nb * 8 + cib;
        int k0 = kk * 16 + 2 * tt + hs * 8;
        float v0 = 0.f, v1 = 0.f;
        if (col < 47) {
            v0 = (k0 < 128) ? w2l[col * 128 + k0] : w2r[col * 128 + k0 - 128];
            v1 = (k0 + 1 < 128) ? w2l[col * 128 + k0 + 1] : w2r[col * 128 + k0 + 1 - 128];
        }
        __half2 h = __floats2half2_rn(v0, v1);
        int dest = (kk >> 1) * 768 + (kk & 1) * 384 + nb * 64 + hs * 32 + cib * 4 + tt;
        g_wT2h[dest] = *reinterpret_cast<u32*>(&h);
    }
    for (int j = t; j < Nn; j += stride) g_cnt[j] = 0;
    if (t < 128) { g_bnsum[t] = 0.f; g_bnsq[t] = 0.f; }
    const float4* x4 = (const float4*)x;
    uint2* out = (uint2*)g_x16;
    int n4 = Nn * 32;
    for (int j = t; j < n4; j += stride) out[j] = pack_h4(x4[j]);
}

__global__ void __launch_bounds__(256) build_adj(
    const void* __restrict__ ei, int E, int Nn)
{
    const int is32 = g_ei32;
    int t = blockIdx.x * blockDim.x + threadIdx.x;
    int stride = gridDim.x * blockDim.x;
    for (int e = t; e < E; e += stride) {
        int src, dst;
        if (is32) {
            src = ((const int*)ei)[e];
            dst = ((const int*)ei)[(size_t)E + e];
        } else {
            src = (int)((const long long*)ei)[e];
            dst = (int)((const long long*)ei)[(size_t)E + e];
        }
        if ((unsigned)src >= (unsigned)Nn || (unsigned)dst >= (unsigned)Nn) continue;
        int pos = atomicAdd(&g_cnt[dst], 1);
        if (pos < SLOTS) g_slot[(size_t)dst * SLOTS + pos] = src;
    }
}

// Gather: one warp per node; lane owns channels 4l..4l+3.
// srcSel=0 (layer 1): agg only, 64-word rows (self comes straight from g_x16).
// srcSel=1 (layer 2): [agg | bnrelu-self], 128-word rows.
__global__ void __launch_bounds__(256, 6) gather_mean(int srcSel, int Nn)
{
    const uint2* feat2 = srcSel ? (const uint2*)g_h16 : (const uint2*)g_x16;
    const int withBN = srcSel;
    int gw   = (blockIdx.x * blockDim.x + threadIdx.x) >> 5;
    int lane = threadIdx.x & 31;
    int nw   = (gridDim.x * blockDim.x) >> 5;
    float4 sc = make_float4(1.f, 1.f, 1.f, 1.f);
    float4 sh = make_float4(0.f, 0.f, 0.f, 0.f);
    if (withBN) {
        sc = ((const float4*)g_bnscale)[lane];
        sh = ((const float4*)g_bnshift)[lane];
    }
    uint2* out2 = (uint2*)g_in16;
    for (int n = gw; n < Nn; n += nw) {
        int cnt = g_cnt[n];
        int m = min(cnt, SLOTS);
        const int* sl = g_slot + (size_t)n * SLOTS;
        float4 a = make_float4(0.f, 0.f, 0.f, 0.f);
        int j = 0;
        for (; j + 4 <= m; j += 4) {
            float4 v0 = unpack_h4(feat2[(size_t)sl[j]     * 32 + lane]);
            float4 v1 = unpack_h4(feat2[(size_t)sl[j + 1] * 32 + lane]);
            float4 v2 = unpack_h4(feat2[(size_t)sl[j + 2] * 32 + lane]);
            float4 v3 = unpack_h4(feat2[(size_t)sl[j + 3] * 32 + lane]);
            if (withBN) {
                v0 = bnrelu4(v0, sc, sh); v1 = bnrelu4(v1, sc, sh);
                v2 = bnrelu4(v2, sc, sh); v3 = bnrelu4(v3, sc, sh);
            }
            a.x += (v0.x + v1.x) + (v2.x + v3.x);
            a.y += (v0.y + v1.y) + (v2.y + v3.y);
            a.z += (v0.z + v1.z) + (v2.z + v3.z);
            a.w += (v0.w + v1.w) + (v2.w + v3.w);
        }
        for (; j < m; j++) {
            float4 v = unpack_h4(feat2[(size_t)sl[j] * 32 + lane]);
            if (withBN) v = bnrelu4(v, sc, sh);
            a.x += v.x; a.y += v.y; a.z += v.z; a.w += v.w;
        }
        float r = 1.f / fmaxf((float)cnt, 1.f);
        a.x *= r; a.y *= r; a.z *= r; a.w *= r;
        if (srcSel) {
            out2[(size_t)n * 64 + lane] = pack_h4(a);
            float4 s = bnrelu4(unpack_h4(feat2[(size_t)n * 32 + lane]), sc, sh);
            out2[(size_t)n * 64 + 32 + lane] = pack_h4(s);
        } else {
            out2[(size_t)n * 32 + lane] = pack_h4(a);
        }
    }
}

// ---------------------------------------------------------------------------
// GEMM1 (fp16 mma m16n8k16, 3-stage cp.async): h = L2norm_row([agg|x] @ W1 + b1l)
// 128 threads = 4 warps (wm,wn 2x2); 64-node x 128-ch tile.
// Inputs: kc<4 from g_in16 (64w agg rows), kc>=4 from g_x16 — all pure cp.async.
// ---------------------------------------------------------------------------
__global__ void __launch_bounds__(128) sage_gemm1(
    const float* __restrict__ bias, int Nn)
{
    extern __shared__ u32 dyn[];
    u32* wSb = dyn;            // 3 * 2048
    u32* iSb = dyn + 6144;     // 3 * 1280
    __shared__ float ssS[2][64];
    __shared__ float bnstage[2][4][128];

    const int tid  = threadIdx.x;
    const int warp = tid >> 5, lane = tid & 31;
    const int wm = warp >> 1, wn = warp & 1;
    const int qr = lane >> 2, qk = lane & 3;

    float2 bp[8];
#pragma unroll
    for (int nb = 0; nb < 8; nb++)
        bp[nb] = *(const float2*)&bias[wn * 64 + nb * 8 + 2 * qk];

    for (int base = blockIdx.x * 64; base < Nn; base += gridDim.x * 64) {
        int nrem = min(64, Nn - base);

        float acc[2][8][4];
#pragma unroll
        for (int mb = 0; mb < 2; mb++)
#pragma unroll
            for (int nb = 0; nb < 8; nb++)
#pragma unroll
                for (int q = 0; q < 4; q++) acc[mb][nb][q] = 0.f;

        auto stage = [&](int kc, int buf) {
            u32* wdst = wSb + buf * 2048;
            const u32* wsrc = g_wT1h + kc * 2048;
            for (int i4 = tid; i4 < 512; i4 += 128) cpa16(&wdst[i4 * 4], &wsrc[i4 * 4]);
            u32* ib = iSb + buf * 1280;
            for (int i = tid; i < 256; i += 128) {
                int n = i >> 2, q = i & 3;
                void* dst = &ib[n * IWSTR + q * 4];
                const void* src = (kc < 4)
                    ? (const void*)&g_in16[(size_t)(base + n) * 64 + kc * 16 + q * 4]
                    : (const void*)&g_x16[(size_t)(base + n) * 64 + (kc - 4) * 16 + q * 4];
                if (n < nrem) cpa16(dst, src);
                else          cpa16_zero(dst, g_x16);
            }
        };

        stage(0, 0); cpa_commit();
        stage(1, 1); cpa_commit();
        for (int kc = 0; kc < 8; kc++) {
            int cur = kc % 3;
            if (kc < 6)      { stage(kc + 2, (kc + 2) % 3); cpa_commit(); cpa_wait<2>(); }
            else if (kc == 6){ cpa_wait<1>(); }
            else             { cpa_wait<0>(); }
            __syncthreads();

            const u32* wS = wSb + cur * 2048;
            const u32* inS = iSb + cur * 1280;
#pragma unroll
            for (int ks = 0; ks < 2; ks++) {
                u32 b0[8], b1[8];
                const uint4* wv = (const uint4*)(wS + ks * 1024 + wn * 512 + lane * 16);
#pragma unroll
                for (int j = 0; j < 4; j++) {
                    uint4 wq = wv[(j + (lane >> 1)) & 3];
                    b0[2 * j]     = wq.x; b1[2 * j]     = wq.y;
                    b0[2 * j + 1] = wq.z; b1[2 * j + 1] = wq.w;
                }
                u32 a[2][4];
#pragma unroll
                for (int mb = 0; mb < 2; mb++) {
                    int r0 = (wm * 32 + mb * 16 + qr) * IWSTR + ks * 8 + qk;
                    int r1 = r0 + 8 * IWSTR;
                    a[mb][0] = inS[r0];
                    a[mb][1] = inS[r1];
                    a[mb][2] = inS[r0 + 4];
                    a[mb][3] = inS[r1 + 4];
                }
#pragma unroll
                for (int mb = 0; mb < 2; mb++)
#pragma unroll
                    for (int nb = 0; nb < 8; nb++)
                        mma_f16(acc[mb][nb], a[mb][0], a[mb][1], a[mb][2], a[mb][3],
                                b0[nb], b1[nb]);
            }
            __syncthreads();
        }

        // Epilogue: bias, row L2 norm, store h (fp16), BN partials (fp32).
        float2 s1[8], s2[8];
#pragma unroll
        for (int nb = 0; nb < 8; nb++) { s1[nb] = make_float2(0.f, 0.f); s2[nb] = make_float2(0.f, 0.f); }

        float ssp[2][2] = {{0.f, 0.f}, {0.f, 0.f}};
#pragma unroll
        for (int mb = 0; mb < 2; mb++)
#pragma unroll
            for (int nb = 0; nb < 8; nb++) {
                acc[mb][nb][0] += bp[nb].x; acc[mb][nb][1] += bp[nb].y;
                acc[mb][nb][2] += bp[nb].x; acc[mb][nb][3] += bp[nb].y;
                ssp[mb][0] += acc[mb][nb][0] * acc[mb][nb][0] + acc[mb][nb][1] * acc[mb][nb][1];
                ssp[mb][1] += acc[mb][nb][2] * acc[mb][nb][2] + acc[mb][nb][3] * acc[mb][nb][3];
            }
#pragma unroll
        for (int mb = 0; mb < 2; mb++)
#pragma unroll
            for (int rs = 0; rs < 2; rs++) {
                ssp[mb][rs] += __shfl_xor_sync(0xffffffffu, ssp[mb][rs], 1);
                ssp[mb][rs] += __shfl_xor_sync(0xffffffffu, ssp[mb][rs], 2);
            }
        if (qk == 0) {
#pragma unroll
            for (int mb = 0; mb < 2; mb++)
#pragma unroll
                for (int rs = 0; rs < 2; rs++)
                    ssS[wn][wm * 32 + mb * 16 + rs * 8 + qr] = ssp[mb][rs];
        }
        __syncthreads();
        float inv[2][2];
#pragma unroll
        for (int mb = 0; mb < 2; mb++)
#pragma unroll
            for (int rs = 0; rs < 2; rs++) {
                int lr = wm * 32 + mb * 16 + rs * 8 + qr;
                float tot = ssS[0][lr] + ssS[1][lr];
                inv[mb][rs] = 1.f / fmaxf(sqrtf(tot), 1e-12f);
            }
#pragma unroll
        for (int mb = 0; mb < 2; mb++) {
            int lr0 = wm * 32 + mb * 16 + qr;
            int lr1 = lr0 + 8;
#pragma unroll
            for (int nb = 0; nb < 8; nb++) {
                int word = wn * 32 + nb * 4 + qk;
                if (lr0 < nrem) {
                    float vx = acc[mb][nb][0] * inv[mb][0];
                    float vy = acc[mb][nb][1] * inv[mb][0];
                    __half2 hv = __floats2half2_rn(vx, vy);
                    g_h16[(size_t)(base + lr0) * 64 + word] = *reinterpret_cast<u32*>(&hv);
                    s1[nb].x += vx; s1[nb].y += vy;
                    s2[nb].x += vx * vx; s2[nb].y += vy * vy;
                }
                if (lr1 < nrem) {
                    float vx = acc[mb][nb][2] * inv[mb][1];
                    float vy = acc[mb][nb][3] * inv[mb][1];
                    __half2 hv = __floats2half2_rn(vx, vy);
                    g_h16[(size_t)(base + lr1) * 64 + word] = *reinterpret_cast<u32*>(&hv);
                    s1[nb].x += vx; s1[nb].y += vy;
                    s2[nb].x += vx * vx; s2[nb].y += vy * vy;
                }
            }
        }

        // BN reduction for this tile.
#pragma unroll
        for (int off = 4; off < 32; off <<= 1) {
#pragma unroll
            for (int nb = 0; nb < 8; nb++) {
                s1[nb].x += __shfl_xor_sync(0xffffffffu, s1[nb].x, off);
                s1[nb].y += __shfl_xor_sync(0xffffffffu, s1[nb].y, off);
                s2[nb].x += __shfl_xor_sync(0xffffffffu, s2[nb].x, off);
                s2[nb].y += __shfl_xor_sync(0xffffffffu, s2[nb].y, off);
            }
        }
        if (lane < 4) {
#pragma unroll
            for (int nb = 0; nb < 8; nb++) {
                int c = wn * 64 + nb * 8 + 2 * lane;
                bnstage[0][warp][c] = s1[nb].x; bnstage[0][warp][c + 1] = s1[nb].y;
                bnstage[1][warp][c] = s2[nb].x; bnstage[1][warp][c + 1] = s2[nb].y;
            }
        }
        __syncthreads();
        if (tid < 128) {
            int wsel = tid >> 6;
            float a0 = bnstage[0][wsel][tid] + bnstage[0][2 + wsel][tid];
            float a1 = bnstage[1][wsel][tid] + bnstage[1][2 + wsel][tid];
            atomicAdd(&g_bnsum[tid], a0);
            atomicAdd(&g_bnsq[tid], a1);
        }
        __syncthreads();
    }
}

__global__ void bn_finalize(const float* __restrict__ gamma, const float* __restrict__ beta, float invN) {
    int c = threadIdx.x;
    float mean = g_bnsum[c] * invN;
    float var = g_bnsq[c] * invN - mean * mean;
    float sc = gamma[c] * rsqrtf(var + 1e-5f);
    g_bnscale[c] = sc;
    g_bnshift[c] = beta[c] - mean * sc;
}

// ---------------------------------------------------------------------------
// GEMM2 (fp16 mma, 2-stage): out = L2norm_row(g_in @ W2 + b2l), 47 cols (48 pad)
// ---------------------------------------------------------------------------
__global__ void __launch_bounds__(128) sage_gemm2(
    const float* __restrict__ b2l, float* __restrict__ outp, int Nn)
{
    extern __shared__ u32 dyn[];
    u32* wSb = dyn;            // 2 * 768
    u32* iSb = dyn + 1536;     // 2 * 1280
    __shared__ float ssS[2][64];

    const int tid  = threadIdx.x;
    const int warp = tid >> 5, lane = tid & 31;
    const int wm = warp >> 1, wn = warp & 1;
    const int qr = lane >> 2, qk = lane & 3;

    float2 bp[3];
#pragma unroll
    for (int nb = 0; nb < 3; nb++) {
        int c = wn * 24 + nb * 8 + 2 * qk;
        bp[nb].x = (c < 47) ? b2l[c] : 0.f;
        bp[nb].y = (c + 1 < 47) ? b2l[c + 1] : 0.f;
    }

    for (int base = blockIdx.x * 64; base < Nn; base += gridDim.x * 64) {
        int nrem = min(64, Nn - base);

        float acc[2][3][4];
#pragma unroll
        for (int mb = 0; mb < 2; mb++)
#pragma unroll
            for (int nb = 0; nb < 3; nb++)
#pragma unroll
                for (int q = 0; q < 4; q++) acc[mb][nb][q] = 0.f;

        auto stage = [&](int kc, int buf) {
            u32* wdst = wSb + buf * 768;
            const u32* wsrc = g_wT2h + kc * 768;
            for (int i4 = tid; i4 < 192; i4 += 128) cpa16(&wdst[i4 * 4], &wsrc[i4 * 4]);
            u32* ib = iSb + buf * 1280;
            for (int i = tid; i < 256; i += 128) {
                int n = i >> 2, q = i & 3;
                void* dst = &ib[n * IWSTR + q * 4];
                const void* src = &g_in16[(size_t)(base + n) * 128 + kc * 16 + q * 4];
                if (n < nrem) cpa16(dst, src);
                else          cpa16_zero(dst, g_in16);
            }
        };

        stage(0, 0);
        cpa_commit();
        for (int kc = 0; kc < 8; kc++) {
            int cur = kc & 1;
            if (kc < 7) { stage(kc + 1, cur ^ 1); cpa_commit(); cpa_wait<1>(); }
            else        { cpa_wait<0>(); }
            __syncthreads();

            const u32* wS = wSb + cur * 768;
            const u32* inS = iSb + cur * 1280;
#pragma unroll
            for (int ks = 0; ks < 2; ks++) {
                u32 b0[3], b1[3];
                int wb0 = ks * 384 + wn * 192 + qr * 4 + qk;
#pragma unroll
                for (int nb = 0; nb < 3; nb++) {
                    b0[nb] = wS[wb0 + nb * 64];
                    b1[nb] = wS[wb0 + nb * 64 + 32];
                }
                u32 a[2][4];
#pragma unroll
                for (int mb = 0; mb < 2; mb++) {
                    int r0 = (wm * 32 + mb * 16 + qr) * IWSTR + ks * 8 + qk;
                    int r1 = r0 + 8 * IWSTR;
                    a[mb][0] = inS[r0];
                    a[mb][1] = inS[r1];
                    a[mb][2] = inS[r0 + 4];
                    a[mb][3] = inS[r1 + 4];
                }
#pragma unroll
                for (int mb = 0; mb < 2; mb++)
#pragma unroll
                    for (int nb = 0; nb < 3; nb++)
                        mma_f16(acc[mb][nb], a[mb][0], a[mb][1], a[mb][2], a[mb][3],
                                b0[nb], b1[nb]);
            }
            __syncthreads();
        }

        float ssp[2][2] = {{0.f, 0.f}, {0.f, 0.f}};
#pragma unroll
        for (int mb = 0; mb < 2; mb++)
#pragma unroll
            for (int nb = 0; nb < 3; nb++) {
                acc[mb][nb][0] += bp[nb].x; acc[mb][nb][1] += bp[nb].y;
                acc[mb][nb][2] += bp[nb].x; acc[mb][nb][3] += bp[nb].y;
                ssp[mb][0] += acc[mb][nb][0] * acc[mb][nb][0] + acc[mb][nb][1] * acc[mb][nb][1];
                ssp[mb][1] += acc[mb][nb][2] * acc[mb][nb][2] + acc[mb][nb][3] * acc[mb][nb][3];
            }
#pragma unroll
        for (int mb = 0; mb < 2; mb++)
#pragma unroll
            for (int rs = 0; rs < 2; rs++) {
                ssp[mb][rs] += __shfl_xor_sync(0xffffffffu, ssp[mb][rs], 1);
                ssp[mb][rs] += __shfl_xor_sync(0xffffffffu, ssp[mb][rs], 2);
            }
        if (qk == 0) {
#pragma unroll
            for (int mb = 0; mb < 2; mb++)
#pragma unroll
                for (int rs = 0; rs < 2; rs++)
                    ssS[wn][wm * 32 + mb * 16 + rs * 8 + qr] = ssp[mb][rs];
        }
        __syncthreads();
        float inv[2][2];
#pragma unroll
        for (int mb = 0; mb < 2; mb++)
#pragma unroll
            for (int rs = 0; rs < 2; rs++) {
                int lr = wm * 32 + mb * 16 + rs * 8 + qr;
                float tot = ssS[0][lr] + ssS[1][lr];
                inv[mb][rs] = 1.f / fmaxf(sqrtf(tot), 1e-12f);
            }
#pragma unroll
        for (int mb = 0; mb < 2; mb++) {
            int lr0 = wm * 32 + mb * 16 + qr;
            int lr1 = lr0 + 8;
#pragma unroll
            for (int nb = 0; nb < 3; nb++) {
                int c0 = wn * 24 + nb * 8 + 2 * qk;
                if (lr0 < nrem) {
                    size_t o = (size_t)(base + lr0) * 47;
                    if (c0 < 47)     outp[o + c0]     = acc[mb][nb][0] * inv[mb][0];
                    if (c0 + 1 < 47) outp[o + c0 + 1] = acc[mb][nb][1] * inv[mb][0];
                }
                if (lr1 < nrem) {
                    size_t o = (size_t)(base + lr1) * 47;
                    if (c0 < 47)     outp[o + c0]     = acc[mb][nb][2] * inv[mb][1];
                    if (c0 + 1 < 47) outp[o + c0 + 1] = acc[mb][nb][3] * inv[mb][1];
                }
            }
        }
        __syncthreads();
    }
}

// ---------------------------------------------------------------------------
extern "C" void kernel_launch(void* const* d_in, const int* in_sizes, int n_in,
                              void* d_out, int out_size) {
    const float* x     = (const float*)d_in[0];
    const void*  ei    = d_in[1];
    const float* w1l   = (const float*)d_in[2];
    const float* b1l   = (const float*)d_in[3];
    const float* w1r   = (const float*)d_in[4];
    const float* gamma = (const float*)d_in[5];
    const float* beta  = (const float*)d_in[6];
    const float* w2l   = (const float*)d_in[7];
    const float* b2l   = (const float*)d_in[8];
    const float* w2r   = (const float*)d_in[9];
    int Nn = in_sizes[0] / 128;
    int E  = in_sizes[1] / 2;

    int gb = (Nn + 63) / 64;
    int smem1 = (3 * 2048 + 3 * 1280) * 4;   // 39936 B
    int smem2 = (2 * 768 + 2 * 1280) * 4;    // 16384 B

    static int attr_done = 0;
    if (!attr_done) {
        cudaFuncSetAttribute(sage_gemm1, cudaFuncAttributeMaxDynamicSharedMemorySize, smem1);
        attr_done = 1;
    }

    prep_all<<<1024, 256>>>(x, ei, w1l, w1r, w2l, w2r, Nn);
    build_adj<<<(E + 255) / 256, 256>>>(ei, E, Nn);
    gather_mean<<<2048, 256>>>(0, Nn);
    sage_gemm1<<<gb, 128, smem1>>>(b1l, Nn);
    bn_finalize<<<1, 128>>>(gamma, beta, 1.0f / (float)Nn);
    gather_mean<<<2048, 256>>>(1, Nn);
    sage_gemm2<<<gb, 128, smem2>>>(b2l, (float*)d_out, Nn);
}